// round 1
// baseline (speedup 1.0000x reference)
#include <cuda_runtime.h>

#define BATCH 4096
#define CIN   64
#define NF    256
#define DOUT  20
#define NTRI  210   // 20*21/2
#define NSWEEP 10

struct SM {
    float xs[NF][68];        // x transposed: xs[n][c], stride 68 (16B aligned, conflict-free)
    float G[CIN][65];        // raw gram, then K in place
    float Wm[CIN][DOUT];     // W staged
    float A64[CIN][DOUT];    // K*W
    float Ae[DOUT][21];      // Y, then diagonalized
    float Ue[DOUT][21];      // eigenvectors
    float rs[CIN][4];        // row-sum partials
    float mean[CIN];
    float sq[CIN];
    float rc[10], rsn[10];   // rotation cos/sin
    float ls[DOUT];          // log eigenvalues
    float v[NTRI];
};

__device__ __forceinline__ void pairpq(int r, int k, int& p, int& q) {
    // round-robin tournament (circle method), 10 disjoint pairs per round
    int a = (k == 0) ? 0 : ((k - 1 + r) % 19) + 1;
    int b = ((18 - k + r) % 19) + 1;     // slot 19-k
    p = min(a, b); q = max(a, b);
}

__global__ __launch_bounds__(256, 2)
void cifarnet_kernel(const float* __restrict__ x, const float* __restrict__ W,
                     const float* __restrict__ lw, const float* __restrict__ lb,
                     float* __restrict__ out)
{
    extern __shared__ char smraw[];
    SM& s = *reinterpret_cast<SM*>(smraw);
    const int b   = blockIdx.x;
    const int tid = threadIdx.x;

    // ---- Phase A: load x[b] transposed into smem + per-row partial sums; stage W ----
    {
        const int c   = tid & 63;
        const int seg = tid >> 6;                 // 4 segments of 64 features
        const float* xp = x + ((size_t)b * CIN + c) * NF + seg * 64;
        float acc = 0.f;
        #pragma unroll
        for (int i = 0; i < 16; ++i) {
            float4 val = *reinterpret_cast<const float4*>(xp + i * 4);
            int n = seg * 64 + i * 4;
            s.xs[n + 0][c] = val.x; s.xs[n + 1][c] = val.y;
            s.xs[n + 2][c] = val.z; s.xs[n + 3][c] = val.w;
            acc += val.x + val.y + val.z + val.w;
        }
        s.rs[c][seg] = acc;
        for (int idx = tid; idx < CIN * DOUT; idx += 256)
            (&s.Wm[0][0])[idx] = W[idx];
    }
    __syncthreads();

    // ---- Phase B: raw gram G = X X^T, 4x4 register tile per thread ----
    const int ty = tid >> 4, tx = tid & 15;
    {
        float acc[4][4];
        #pragma unroll
        for (int i = 0; i < 4; ++i)
            #pragma unroll
            for (int j = 0; j < 4; ++j) acc[i][j] = 0.f;

        #pragma unroll 8
        for (int n = 0; n < NF; ++n) {
            float4 af = *reinterpret_cast<const float4*>(&s.xs[n][4 * ty]);
            float4 bf = *reinterpret_cast<const float4*>(&s.xs[n][4 * tx]);
            float av[4] = {af.x, af.y, af.z, af.w};
            float bv[4] = {bf.x, bf.y, bf.z, bf.w};
            #pragma unroll
            for (int i = 0; i < 4; ++i)
                #pragma unroll
                for (int j = 0; j < 4; ++j)
                    acc[i][j] = fmaf(av[i], bv[j], acc[i][j]);
        }
        #pragma unroll
        for (int i = 0; i < 4; ++i)
            #pragma unroll
            for (int j = 0; j < 4; ++j)
                s.G[4 * ty + i][4 * tx + j] = acc[i][j];
    }
    __syncthreads();

    // ---- Phase C: means + sq ----
    if (tid < CIN) {
        float m = (s.rs[tid][0] + s.rs[tid][1] + s.rs[tid][2] + s.rs[tid][3]) * (1.f / NF);
        s.mean[tid] = m;
        s.sq[tid]   = s.G[tid][tid] - (float)NF * m * m;
    }
    __syncthreads();

    // ---- Phase D: K = exp(-50 * d2), in place over G (own 4x4 block only) ----
    {
        #pragma unroll
        for (int i = 0; i < 4; ++i) {
            int c = 4 * ty + i;
            float mc = s.mean[c], sc = s.sq[c];
            #pragma unroll
            for (int j = 0; j < 4; ++j) {
                int d = 4 * tx + j;
                float g  = s.G[c][d] - (float)NF * mc * s.mean[d];
                float d2 = fmaxf(sc + s.sq[d] - 2.f * g, 0.f) * (1.f / NF);
                s.G[c][d] = __expf(-50.f * d2);
            }
        }
    }
    __syncthreads();

    // ---- Phase E: A64 = K * W  (64x20) ----
    {
        const int c  = tid >> 2;
        const int j0 = (tid & 3) * 5;
        float a0 = 0.f, a1 = 0.f, a2 = 0.f, a3 = 0.f, a4 = 0.f;
        #pragma unroll 4
        for (int d = 0; d < CIN; ++d) {
            float kk = s.G[c][d];
            a0 = fmaf(kk, s.Wm[d][j0 + 0], a0);
            a1 = fmaf(kk, s.Wm[d][j0 + 1], a1);
            a2 = fmaf(kk, s.Wm[d][j0 + 2], a2);
            a3 = fmaf(kk, s.Wm[d][j0 + 3], a3);
            a4 = fmaf(kk, s.Wm[d][j0 + 4], a4);
        }
        s.A64[c][j0 + 0] = a0; s.A64[c][j0 + 1] = a1; s.A64[c][j0 + 2] = a2;
        s.A64[c][j0 + 3] = a3; s.A64[c][j0 + 4] = a4;
    }
    __syncthreads();

    // ---- Phase F: Y = W^T * A64 (20x20, symmetric by construction); init U = I ----
    for (int t = tid; t < NTRI; t += 256) {
        int i = 0, rem = t;
        while (rem >= DOUT - i) { rem -= DOUT - i; ++i; }
        int j = i + rem;
        float acc = 0.f;
        #pragma unroll 4
        for (int c = 0; c < CIN; ++c)
            acc = fmaf(s.Wm[c][i], s.A64[c][j], acc);
        s.Ae[i][j] = acc;
        s.Ae[j][i] = acc;
    }
    for (int t = tid; t < DOUT * DOUT; t += 256)
        s.Ue[t / DOUT][t % DOUT] = (t / DOUT == t % DOUT) ? 1.f : 0.f;
    __syncthreads();

    // ---- Phase G: parallel two-sided Jacobi eigensolver ----
    for (int sweep = 0; sweep < NSWEEP; ++sweep) {
        for (int r = 0; r < 19; ++r) {
            if (tid < 10) {
                int p, q; pairpq(r, tid, p, q);
                float app = s.Ae[p][p], aqq = s.Ae[q][q], apq = s.Ae[p][q];
                float c1, s1;
                if (fabsf(apq) > 1e-30f) {
                    float th = 0.5f * (aqq - app) / apq;
                    float t1 = copysignf(1.f, th) / (fabsf(th) + sqrtf(th * th + 1.f));
                    c1 = rsqrtf(t1 * t1 + 1.f);
                    s1 = t1 * c1;
                } else { c1 = 1.f; s1 = 0.f; }
                s.rc[tid] = c1; s.rsn[tid] = s1;
            }
            __syncthreads();
            if (tid < 200) {                       // row rotations: A <- J^T A
                int k = tid / 20, j = tid % 20;
                int p, q; pairpq(r, k, p, q);
                float c1 = s.rc[k], s1 = s.rsn[k];
                float ap = s.Ae[p][j], aq = s.Ae[q][j];
                s.Ae[p][j] = c1 * ap - s1 * aq;
                s.Ae[q][j] = s1 * ap + c1 * aq;
            }
            __syncthreads();
            if (tid < 200) {                       // col rotations: A <- A J ; U <- U J
                int k = tid / 20, i = tid % 20;
                int p, q; pairpq(r, k, p, q);
                float c1 = s.rc[k], s1 = s.rsn[k];
                float ap = s.Ae[i][p], aq = s.Ae[i][q];
                s.Ae[i][p] = c1 * ap - s1 * aq;
                s.Ae[i][q] = s1 * ap + c1 * aq;
                float up = s.Ue[i][p], uq = s.Ue[i][q];
                s.Ue[i][p] = c1 * up - s1 * uq;
                s.Ue[i][q] = s1 * up + c1 * uq;
            }
            __syncthreads();
        }
    }

    // ---- Phase H: log eigenvalues, M = U logS U^T (triu), linear head ----
    if (tid < DOUT)
        s.ls[tid] = logf(fmaxf(s.Ae[tid][tid], 1e-4f));
    __syncthreads();

    for (int t = tid; t < NTRI; t += 256) {
        int i = 0, rem = t;
        while (rem >= DOUT - i) { rem -= DOUT - i; ++i; }
        int j = i + rem;
        float acc = 0.f;
        #pragma unroll
        for (int m = 0; m < DOUT; ++m)
            acc = fmaf(s.Ue[i][m] * s.ls[m], s.Ue[j][m], acc);
        s.v[t] = acc;
    }
    __syncthreads();

    if (tid < 10) {
        float acc = lb[tid];
        #pragma unroll 6
        for (int t = 0; t < NTRI; ++t)
            acc = fmaf(s.v[t], lw[tid * NTRI + t], acc);
        out[(size_t)b * 10 + tid] = acc;
    }
}

extern "C" void kernel_launch(void* const* d_in, const int* in_sizes, int n_in,
                              void* d_out, int out_size) {
    const float* x  = (const float*)d_in[0];
    const float* W  = (const float*)d_in[1];
    const float* lw = (const float*)d_in[2];
    const float* lb = (const float*)d_in[3];
    float* out = (float*)d_out;

    cudaFuncSetAttribute(cifarnet_kernel,
                         cudaFuncAttributeMaxDynamicSharedMemorySize,
                         (int)sizeof(SM));
    cifarnet_kernel<<<BATCH, 256, sizeof(SM)>>>(x, W, lw, lb, out);
}

// round 3
// speedup vs baseline: 1.2713x; 1.2713x over previous
#include <cuda_runtime.h>

#define BATCH 4096
#define CIN   64
#define NF    256
#define DOUT  20
#define NTRI  210
#define NSWEEP 10

// ---------------- scratch: Y matrices, layout Ysc[b*400 + j*20 + i] = Y[i][j]
__device__ float Ysc[BATCH * DOUT * DOUT];

// ================= K1: gram + kernel matrix + Y = W^T K W =================
struct SM1 {
    float xs[128][68];     // chunk of x transposed: xs[n][c]
    float G[CIN][65];      // raw gram, then K in place
    float Wm[CIN][DOUT];
    float A64[CIN][DOUT];  // K*W
    float rs[CIN][4];
    float mean[CIN];
    float sq[CIN];
};

__global__ __launch_bounds__(256, 3)
void gram_kernel(const float* __restrict__ x, const float* __restrict__ W)
{
    extern __shared__ char smraw[];
    SM1& s = *reinterpret_cast<SM1*>(smraw);
    const int b   = blockIdx.x;
    const int tid = threadIdx.x;
    const int c   = tid & 63;
    const int s2  = tid >> 6;          // 0..3
    const int ty  = tid >> 4, tx = tid & 15;

    // stage W
    for (int idx = tid; idx < CIN * DOUT; idx += 256)
        (&s.Wm[0][0])[idx] = W[idx];

    float acc[4][4];
    #pragma unroll
    for (int i = 0; i < 4; ++i)
        #pragma unroll
        for (int j = 0; j < 4; ++j) acc[i][j] = 0.f;
    float sumacc = 0.f;

    // two 128-feature chunks
    for (int ch = 0; ch < 2; ++ch) {
        const float* xp = x + ((size_t)b * CIN + c) * NF + ch * 128 + s2 * 32;
        #pragma unroll
        for (int i = 0; i < 8; ++i) {
            float4 v = *reinterpret_cast<const float4*>(xp + 4 * i);
            int n = s2 * 32 + 4 * i;
            s.xs[n + 0][c] = v.x; s.xs[n + 1][c] = v.y;
            s.xs[n + 2][c] = v.z; s.xs[n + 3][c] = v.w;
            sumacc += v.x + v.y + v.z + v.w;
        }
        __syncthreads();
        #pragma unroll 8
        for (int n = 0; n < 128; ++n) {
            float4 af = *reinterpret_cast<const float4*>(&s.xs[n][4 * ty]);
            float4 bf = *reinterpret_cast<const float4*>(&s.xs[n][4 * tx]);
            float av[4] = {af.x, af.y, af.z, af.w};
            float bv[4] = {bf.x, bf.y, bf.z, bf.w};
            #pragma unroll
            for (int i = 0; i < 4; ++i)
                #pragma unroll
                for (int j = 0; j < 4; ++j)
                    acc[i][j] = fmaf(av[i], bv[j], acc[i][j]);
        }
        __syncthreads();
    }

    s.rs[c][s2] = sumacc;
    #pragma unroll
    for (int i = 0; i < 4; ++i)
        #pragma unroll
        for (int j = 0; j < 4; ++j)
            s.G[4 * ty + i][4 * tx + j] = acc[i][j];
    __syncthreads();

    if (tid < CIN) {
        float m = (s.rs[tid][0] + s.rs[tid][1] + s.rs[tid][2] + s.rs[tid][3]) * (1.f / NF);
        s.mean[tid] = m;
        s.sq[tid]   = s.G[tid][tid] - (float)NF * m * m;
    }
    __syncthreads();

    // K = exp(-50 * d2) in place (own 4x4 block)
    #pragma unroll
    for (int i = 0; i < 4; ++i) {
        int cc = 4 * ty + i;
        float mc = s.mean[cc], sc = s.sq[cc];
        #pragma unroll
        for (int j = 0; j < 4; ++j) {
            int d = 4 * tx + j;
            float g  = s.G[cc][d] - (float)NF * mc * s.mean[d];
            float d2 = fmaxf(sc + s.sq[d] - 2.f * g, 0.f) * (1.f / NF);
            s.G[cc][d] = __expf(-50.f * d2);
        }
    }
    __syncthreads();

    // A64 = K * W
    {
        const int cr = tid >> 2;
        const int j0 = (tid & 3) * 5;
        float a0 = 0.f, a1 = 0.f, a2 = 0.f, a3 = 0.f, a4 = 0.f;
        #pragma unroll 4
        for (int d = 0; d < CIN; ++d) {
            float kk = s.G[cr][d];
            a0 = fmaf(kk, s.Wm[d][j0 + 0], a0);
            a1 = fmaf(kk, s.Wm[d][j0 + 1], a1);
            a2 = fmaf(kk, s.Wm[d][j0 + 2], a2);
            a3 = fmaf(kk, s.Wm[d][j0 + 3], a3);
            a4 = fmaf(kk, s.Wm[d][j0 + 4], a4);
        }
        s.A64[cr][j0 + 0] = a0; s.A64[cr][j0 + 1] = a1; s.A64[cr][j0 + 2] = a2;
        s.A64[cr][j0 + 3] = a3; s.A64[cr][j0 + 4] = a4;
    }
    __syncthreads();

    // Y = W^T * A64 (symmetric) -> global scratch, column-friendly layout
    for (int t = tid; t < NTRI; t += 256) {
        int i = 0, rem = t;
        while (rem >= DOUT - i) { rem -= DOUT - i; ++i; }
        int j = i + rem;
        float a = 0.f;
        #pragma unroll 4
        for (int cc = 0; cc < CIN; ++cc)
            a = fmaf(s.Wm[cc][i], s.A64[cc][j], a);
        Ysc[(size_t)b * 400 + j * 20 + i] = a;
        Ysc[(size_t)b * 400 + i * 20 + j] = a;
    }
}

// ================= K2: warp-per-matrix Jacobi + log + head =================
struct Sched { int p[19][10]; int q[19][10]; };
__host__ __device__ constexpr Sched mksched() {
    Sched s{};
    for (int r = 0; r < 19; ++r)
        for (int k = 0; k < 10; ++k) {
            int a = (k == 0) ? 0 : ((k - 1 + r) % 19) + 1;
            int b = ((18 - k + r) % 19) + 1;
            s.p[r][k] = a < b ? a : b;
            s.q[r][k] = a > b ? a : b;
        }
    return s;
}

__global__ __launch_bounds__(256, 2)
void eig_kernel(const float* __restrict__ lw, const float* __restrict__ lb,
                float* __restrict__ out)
{
    constexpr Sched S = mksched();
    const int w    = threadIdx.x >> 5;
    const int lane = threadIdx.x & 31;
    const int b    = blockIdx.x * 8 + w;

    __shared__ float Usm[8][DOUT][21];
    __shared__ float Vsm[8][DOUT][21];

    float a[DOUT], u[DOUT];
    #pragma unroll
    for (int j = 0; j < DOUT; ++j) {
        a[j] = (lane < DOUT) ? Ysc[(size_t)b * 400 + j * 20 + lane] : 0.f;
        u[j] = (lane == j) ? 1.f : 0.f;
    }

    #pragma unroll 1
    for (int sweep = 0; sweep < NSWEEP; ++sweep) {
        #pragma unroll
        for (int r = 0; r < 19; ++r) {
            float cc[10], ss[10];
            float cr = 1.f, tr = 0.f;
            int prt = lane;
            // rotation angles for all 10 disjoint pairs (from current A)
            #pragma unroll
            for (int k = 0; k < 10; ++k) {
                const int P = S.p[r][k], Q = S.q[r][k];
                float app = __shfl_sync(0xffffffffu, a[P], P);
                float aqq = __shfl_sync(0xffffffffu, a[Q], Q);
                float apq = __shfl_sync(0xffffffffu, a[Q], P);
                float c1, s1;
                if (fabsf(apq) > 1e-30f) {
                    float th = 0.5f * (aqq - app) * __frcp_rn(apq);
                    float t1 = copysignf(1.f, th) * __frcp_rn(fabsf(th) + sqrtf(fmaf(th, th, 1.f)));
                    c1 = rsqrtf(fmaf(t1, t1, 1.f));
                    s1 = t1 * c1;
                } else { c1 = 1.f; s1 = 0.f; }
                cc[k] = c1; ss[k] = s1;
                if (lane == P) { cr = c1; tr = -s1; prt = Q; }
                if (lane == Q) { cr = c1; tr =  s1; prt = P; }
            }
            // row phase: A <- J^T A  (perfect matching, all lanes active)
            #pragma unroll
            for (int j = 0; j < DOUT; ++j) {
                float o = __shfl_sync(0xffffffffu, a[j], prt);
                a[j] = fmaf(cr, a[j], tr * o);
            }
            // col phase: A <- A J ; U <- U J (lane-local)
            #pragma unroll
            for (int k = 0; k < 10; ++k) {
                const int P = S.p[r][k], Q = S.q[r][k];
                float c1 = cc[k], s1 = ss[k];
                float ap = a[P], aq = a[Q];
                a[P] = fmaf(c1, ap, -s1 * aq);
                a[Q] = fmaf(s1, ap,  c1 * aq);
                float up = u[P], uq = u[Q];
                u[P] = fmaf(c1, up, -s1 * uq);
                u[Q] = fmaf(s1, up,  c1 * uq);
            }
        }
    }

    // eigenvalue of this lane's row = diagonal element
    float lam = 1.f;
    #pragma unroll
    for (int j = 0; j < DOUT; ++j)
        if (lane == j) lam = a[j];
    float ls = logf(fmaxf(lam, 1e-4f));

    // stage U and U*diag(logS) rows to smem
    #pragma unroll
    for (int j = 0; j < DOUT; ++j) {
        float lj = __shfl_sync(0xffffffffu, ls, j);
        if (lane < DOUT) {
            Usm[w][lane][j] = u[j];
            Vsm[w][lane][j] = u[j] * lj;
        }
    }
    __syncwarp();

    // triu(M) entries + linear head partials
    float res[10];
    #pragma unroll
    for (int o = 0; o < 10; ++o) res[o] = 0.f;

    for (int t = lane; t < NTRI; t += 32) {
        int i = 0, rem = t;
        while (rem >= DOUT - i) { rem -= DOUT - i; ++i; }
        int j = i + rem;
        float acc = 0.f;
        #pragma unroll
        for (int m = 0; m < DOUT; ++m)
            acc = fmaf(Vsm[w][i][m], Usm[w][j][m], acc);
        #pragma unroll
        for (int o = 0; o < 10; ++o)
            res[o] = fmaf(acc, lw[o * NTRI + t], res[o]);
    }
    // warp reduction
    #pragma unroll
    for (int o = 0; o < 10; ++o) {
        #pragma unroll
        for (int d = 16; d > 0; d >>= 1)
            res[o] += __shfl_xor_sync(0xffffffffu, res[o], d);
    }
    #pragma unroll
    for (int o = 0; o < 10; ++o)
        if (lane == o) out[(size_t)b * 10 + o] = res[o] + lb[o];
}

// ================= launch =================
extern "C" void kernel_launch(void* const* d_in, const int* in_sizes, int n_in,
                              void* d_out, int out_size) {
    const float* x  = (const float*)d_in[0];
    const float* W  = (const float*)d_in[1];
    const float* lw = (const float*)d_in[2];
    const float* lb = (const float*)d_in[3];
    float* out = (float*)d_out;

    cudaFuncSetAttribute(gram_kernel,
                         cudaFuncAttributeMaxDynamicSharedMemorySize,
                         (int)sizeof(SM1));
    gram_kernel<<<BATCH, 256, sizeof(SM1)>>>(x, W);
    eig_kernel<<<BATCH / 8, 256>>>(lw, lb, out);
}

// round 9
// speedup vs baseline: 1.3010x; 1.0234x over previous
#include <cuda_runtime.h>

#define BATCH 4096
#define CIN   64
#define NF    256
#define DOUT  20
#define NTRI  210
#define NSWEEP 10

// ---------------- scratch: Y matrices, layout Ysc[b*400 + j*20 + i] = Y[i][j]
__device__ float Ysc[BATCH * DOUT * DOUT];

// ================= K1: gram + kernel matrix + Y = W^T K W =================
struct SM1 {
    float xs[128][68];
    float G[CIN][65];
    float Wm[CIN][DOUT];
    float A64[CIN][DOUT];
    float rs[CIN][4];
    float mean[CIN];
    float sq[CIN];
};

__global__ __launch_bounds__(256, 3)
void gram_kernel(const float* __restrict__ x, const float* __restrict__ W)
{
    extern __shared__ char smraw[];
    SM1& s = *reinterpret_cast<SM1*>(smraw);
    const int b   = blockIdx.x;
    const int tid = threadIdx.x;
    const int c   = tid & 63;
    const int s2  = tid >> 6;
    const int ty  = tid >> 4, tx = tid & 15;

    for (int idx = tid; idx < CIN * DOUT; idx += 256)
        (&s.Wm[0][0])[idx] = W[idx];

    float acc[4][4];
    #pragma unroll
    for (int i = 0; i < 4; ++i)
        #pragma unroll
        for (int j = 0; j < 4; ++j) acc[i][j] = 0.f;
    float sumacc = 0.f;

    for (int ch = 0; ch < 2; ++ch) {
        const float* xp = x + ((size_t)b * CIN + c) * NF + ch * 128 + s2 * 32;
        #pragma unroll
        for (int i = 0; i < 8; ++i) {
            float4 v = *reinterpret_cast<const float4*>(xp + 4 * i);
            int n = s2 * 32 + 4 * i;
            s.xs[n + 0][c] = v.x; s.xs[n + 1][c] = v.y;
            s.xs[n + 2][c] = v.z; s.xs[n + 3][c] = v.w;
            sumacc += v.x + v.y + v.z + v.w;
        }
        __syncthreads();
        #pragma unroll 8
        for (int n = 0; n < 128; ++n) {
            float4 af = *reinterpret_cast<const float4*>(&s.xs[n][4 * ty]);
            float4 bf = *reinterpret_cast<const float4*>(&s.xs[n][4 * tx]);
            float av[4] = {af.x, af.y, af.z, af.w};
            float bv[4] = {bf.x, bf.y, bf.z, bf.w};
            #pragma unroll
            for (int i = 0; i < 4; ++i)
                #pragma unroll
                for (int j = 0; j < 4; ++j)
                    acc[i][j] = fmaf(av[i], bv[j], acc[i][j]);
        }
        __syncthreads();
    }

    s.rs[c][s2] = sumacc;
    #pragma unroll
    for (int i = 0; i < 4; ++i)
        #pragma unroll
        for (int j = 0; j < 4; ++j)
            s.G[4 * ty + i][4 * tx + j] = acc[i][j];
    __syncthreads();

    if (tid < CIN) {
        float m = (s.rs[tid][0] + s.rs[tid][1] + s.rs[tid][2] + s.rs[tid][3]) * (1.f / NF);
        s.mean[tid] = m;
        s.sq[tid]   = s.G[tid][tid] - (float)NF * m * m;
    }
    __syncthreads();

    #pragma unroll
    for (int i = 0; i < 4; ++i) {
        int cc = 4 * ty + i;
        float mc = s.mean[cc], sc = s.sq[cc];
        #pragma unroll
        for (int j = 0; j < 4; ++j) {
            int d = 4 * tx + j;
            float g  = s.G[cc][d] - (float)NF * mc * s.mean[d];
            float d2 = fmaxf(sc + s.sq[d] - 2.f * g, 0.f) * (1.f / NF);
            s.G[cc][d] = __expf(-50.f * d2);
        }
    }
    __syncthreads();

    {
        const int cr = tid >> 2;
        const int j0 = (tid & 3) * 5;
        float a0 = 0.f, a1 = 0.f, a2 = 0.f, a3 = 0.f, a4 = 0.f;
        #pragma unroll 4
        for (int d = 0; d < CIN; ++d) {
            float kk = s.G[cr][d];
            a0 = fmaf(kk, s.Wm[d][j0 + 0], a0);
            a1 = fmaf(kk, s.Wm[d][j0 + 1], a1);
            a2 = fmaf(kk, s.Wm[d][j0 + 2], a2);
            a3 = fmaf(kk, s.Wm[d][j0 + 3], a3);
            a4 = fmaf(kk, s.Wm[d][j0 + 4], a4);
        }
        s.A64[cr][j0 + 0] = a0; s.A64[cr][j0 + 1] = a1; s.A64[cr][j0 + 2] = a2;
        s.A64[cr][j0 + 3] = a3; s.A64[cr][j0 + 4] = a4;
    }
    __syncthreads();

    for (int t = tid; t < NTRI; t += 256) {
        int i = 0, rem = t;
        while (rem >= DOUT - i) { rem -= DOUT - i; ++i; }
        int j = i + rem;
        float a = 0.f;
        #pragma unroll 4
        for (int cc = 0; cc < CIN; ++cc)
            a = fmaf(s.Wm[cc][i], s.A64[cc][j], a);
        Ysc[(size_t)b * 400 + j * 20 + i] = a;
        Ysc[(size_t)b * 400 + i * 20 + j] = a;
    }
}

// ================= K2: warp-per-matrix Jacobi (round-3 proven structure) =================
// Change vs round 3: replicated diagonal dg[20] in every lane (NR-style), updated
// per pair via the Rutishauser formula. Removes 20 of 30 angle-gather shfls.
struct Sched { int p[19][10]; int q[19][10]; };
__host__ __device__ constexpr Sched mksched() {
    Sched s{};
    for (int r = 0; r < 19; ++r)
        for (int k = 0; k < 10; ++k) {
            int a = (k == 0) ? 0 : ((k - 1 + r) % 19) + 1;
            int b = ((18 - k + r) % 19) + 1;
            s.p[r][k] = a < b ? a : b;
            s.q[r][k] = a > b ? a : b;
        }
    return s;
}

__global__ __launch_bounds__(256)
void eig_kernel(const float* __restrict__ lw, const float* __restrict__ lb,
                float* __restrict__ out)
{
    constexpr Sched S = mksched();
    const int w    = threadIdx.x >> 5;
    const int lane = threadIdx.x & 31;
    const int b    = blockIdx.x * 8 + w;

    __shared__ float Usm[8][DOUT][21];
    __shared__ float Vsm[8][DOUT][21];

    float a[DOUT], u[DOUT];
    #pragma unroll
    for (int j = 0; j < DOUT; ++j) {
        a[j] = (lane < DOUT) ? Ysc[(size_t)b * 400 + j * 20 + lane] : 0.f;
        u[j] = (lane == j) ? 1.f : 0.f;
    }

    // replicated diagonal: dg[j] = A[j][j] in every lane (static indices)
    float dg[DOUT];
    #pragma unroll
    for (int j = 0; j < DOUT; ++j)
        dg[j] = __shfl_sync(0xffffffffu, a[j], j);

    #pragma unroll 1
    for (int sweep = 0; sweep < NSWEEP; ++sweep) {
        #pragma unroll
        for (int r = 0; r < 19; ++r) {
            float cc[10], ss[10];
            float cr = 1.f, tr = 0.f;
            int prt = lane;
            // rotation angles for all 10 disjoint pairs (round-3 math; diag from dg)
            #pragma unroll
            for (int k = 0; k < 10; ++k) {
                const int P = S.p[r][k], Q = S.q[r][k];
                float app = dg[P];
                float aqq = dg[Q];
                float apq = __shfl_sync(0xffffffffu, a[Q], P);
                float c1, s1, t1v = 0.f;
                if (fabsf(apq) > 1e-30f) {
                    float th = 0.5f * (aqq - app) * __frcp_rn(apq);
                    float t1 = copysignf(1.f, th) * __frcp_rn(fabsf(th) + sqrtf(fmaf(th, th, 1.f)));
                    c1 = rsqrtf(fmaf(t1, t1, 1.f));
                    s1 = t1 * c1;
                    t1v = t1;
                } else { c1 = 1.f; s1 = 0.f; }
                cc[k] = c1; ss[k] = s1;
                // Rutishauser diagonal update (local, disjoint pairs)
                dg[P] = app - t1v * apq;
                dg[Q] = aqq + t1v * apq;
                if (lane == P) { cr = c1; tr = -s1; prt = Q; }
                if (lane == Q) { cr = c1; tr =  s1; prt = P; }
            }
            // row phase: A <- J^T A  (perfect matching, all lanes active)
            #pragma unroll
            for (int j = 0; j < DOUT; ++j) {
                float o = __shfl_sync(0xffffffffu, a[j], prt);
                a[j] = fmaf(cr, a[j], tr * o);
            }
            // col phase: A <- A J ; U <- U J (lane-local)
            #pragma unroll
            for (int k = 0; k < 10; ++k) {
                const int P = S.p[r][k], Q = S.q[r][k];
                float c1 = cc[k], s1 = ss[k];
                float ap = a[P], aq = a[Q];
                a[P] = fmaf(c1, ap, -s1 * aq);
                a[Q] = fmaf(s1, ap,  c1 * aq);
                float up = u[P], uq = u[Q];
                u[P] = fmaf(c1, up, -s1 * uq);
                u[Q] = fmaf(s1, up,  c1 * uq);
            }
        }
    }

    // eigenvalue of this lane's row = diagonal element (round-3 path)
    float lam = 1.f;
    #pragma unroll
    for (int j = 0; j < DOUT; ++j)
        if (lane == j) lam = a[j];
    float ls = logf(fmaxf(lam, 1e-4f));

    // stage U and U*diag(logS) rows to smem
    #pragma unroll
    for (int j = 0; j < DOUT; ++j) {
        float lj = __shfl_sync(0xffffffffu, ls, j);
        if (lane < DOUT) {
            Usm[w][lane][j] = u[j];
            Vsm[w][lane][j] = u[j] * lj;
        }
    }
    __syncwarp();

    // triu(M) entries + linear head partials
    float res[10];
    #pragma unroll
    for (int o = 0; o < 10; ++o) res[o] = 0.f;

    for (int t = lane; t < NTRI; t += 32) {
        int i = 0, rem = t;
        while (rem >= DOUT - i) { rem -= DOUT - i; ++i; }
        int j = i + rem;
        float acc = 0.f;
        #pragma unroll
        for (int m = 0; m < DOUT; ++m)
            acc = fmaf(Vsm[w][i][m], Usm[w][j][m], acc);
        #pragma unroll
        for (int o = 0; o < 10; ++o)
            res[o] = fmaf(acc, lw[o * NTRI + t], res[o]);
    }
    // warp reduction
    #pragma unroll
    for (int o = 0; o < 10; ++o) {
        #pragma unroll
        for (int d = 16; d > 0; d >>= 1)
            res[o] += __shfl_xor_sync(0xffffffffu, res[o], d);
    }
    #pragma unroll
    for (int o = 0; o < 10; ++o)
        if (lane == o) out[(size_t)b * 10 + o] = res[o] + lb[o];
}

// ================= launch =================
extern "C" void kernel_launch(void* const* d_in, const int* in_sizes, int n_in,
                              void* d_out, int out_size) {
    const float* x  = (const float*)d_in[0];
    const float* W  = (const float*)d_in[1];
    const float* lw = (const float*)d_in[2];
    const float* lb = (const float*)d_in[3];
    float* out = (float*)d_out;

    cudaFuncSetAttribute(gram_kernel,
                         cudaFuncAttributeMaxDynamicSharedMemorySize,
                         (int)sizeof(SM1));
    gram_kernel<<<BATCH, 256, sizeof(SM1)>>>(x, W);
    eig_kernel<<<BATCH / 8, 256>>>(lw, lb, out);
}

// round 10
// speedup vs baseline: 1.3285x; 1.0212x over previous
#include <cuda_runtime.h>

#define BATCH 4096
#define CIN   64
#define NF    256
#define DOUT  20
#define NTRI  210
#define NSWEEP 10

// ---------------- scratch: Y matrices, layout Ysc[b*400 + j*20 + i] = Y[i][j]
__device__ float Ysc[BATCH * DOUT * DOUT];

// ================= K1: gram + kernel matrix + Y = W^T K W =================
struct SM1 {
    float xs[128][68];
    float G[CIN][65];
    float Wm[CIN][DOUT];
    float A64[CIN][DOUT];
    float rs[CIN][4];
    float mean[CIN];
    float sq[CIN];
};

__global__ __launch_bounds__(256, 3)
void gram_kernel(const float* __restrict__ x, const float* __restrict__ W)
{
    extern __shared__ char smraw[];
    SM1& s = *reinterpret_cast<SM1*>(smraw);
    const int b   = blockIdx.x;
    const int tid = threadIdx.x;
    const int c   = tid & 63;
    const int s2  = tid >> 6;
    const int ty  = tid >> 4, tx = tid & 15;

    for (int idx = tid; idx < CIN * DOUT; idx += 256)
        (&s.Wm[0][0])[idx] = W[idx];

    float acc[4][4];
    #pragma unroll
    for (int i = 0; i < 4; ++i)
        #pragma unroll
        for (int j = 0; j < 4; ++j) acc[i][j] = 0.f;
    float sumacc = 0.f;

    for (int ch = 0; ch < 2; ++ch) {
        const float* xp = x + ((size_t)b * CIN + c) * NF + ch * 128 + s2 * 32;
        #pragma unroll
        for (int i = 0; i < 8; ++i) {
            float4 v = *reinterpret_cast<const float4*>(xp + 4 * i);
            int n = s2 * 32 + 4 * i;
            s.xs[n + 0][c] = v.x; s.xs[n + 1][c] = v.y;
            s.xs[n + 2][c] = v.z; s.xs[n + 3][c] = v.w;
            sumacc += v.x + v.y + v.z + v.w;
        }
        __syncthreads();
        #pragma unroll 8
        for (int n = 0; n < 128; ++n) {
            float4 af = *reinterpret_cast<const float4*>(&s.xs[n][4 * ty]);
            float4 bf = *reinterpret_cast<const float4*>(&s.xs[n][4 * tx]);
            float av[4] = {af.x, af.y, af.z, af.w};
            float bv[4] = {bf.x, bf.y, bf.z, bf.w};
            #pragma unroll
            for (int i = 0; i < 4; ++i)
                #pragma unroll
                for (int j = 0; j < 4; ++j)
                    acc[i][j] = fmaf(av[i], bv[j], acc[i][j]);
        }
        __syncthreads();
    }

    s.rs[c][s2] = sumacc;
    #pragma unroll
    for (int i = 0; i < 4; ++i)
        #pragma unroll
        for (int j = 0; j < 4; ++j)
            s.G[4 * ty + i][4 * tx + j] = acc[i][j];
    __syncthreads();

    if (tid < CIN) {
        float m = (s.rs[tid][0] + s.rs[tid][1] + s.rs[tid][2] + s.rs[tid][3]) * (1.f / NF);
        s.mean[tid] = m;
        s.sq[tid]   = s.G[tid][tid] - (float)NF * m * m;
    }
    __syncthreads();

    #pragma unroll
    for (int i = 0; i < 4; ++i) {
        int cc = 4 * ty + i;
        float mc = s.mean[cc], sc = s.sq[cc];
        #pragma unroll
        for (int j = 0; j < 4; ++j) {
            int d = 4 * tx + j;
            float g  = s.G[cc][d] - (float)NF * mc * s.mean[d];
            float d2 = fmaxf(sc + s.sq[d] - 2.f * g, 0.f) * (1.f / NF);
            s.G[cc][d] = __expf(-50.f * d2);
        }
    }
    __syncthreads();

    {
        const int cr = tid >> 2;
        const int j0 = (tid & 3) * 5;
        float a0 = 0.f, a1 = 0.f, a2 = 0.f, a3 = 0.f, a4 = 0.f;
        #pragma unroll 4
        for (int d = 0; d < CIN; ++d) {
            float kk = s.G[cr][d];
            a0 = fmaf(kk, s.Wm[d][j0 + 0], a0);
            a1 = fmaf(kk, s.Wm[d][j0 + 1], a1);
            a2 = fmaf(kk, s.Wm[d][j0 + 2], a2);
            a3 = fmaf(kk, s.Wm[d][j0 + 3], a3);
            a4 = fmaf(kk, s.Wm[d][j0 + 4], a4);
        }
        s.A64[cr][j0 + 0] = a0; s.A64[cr][j0 + 1] = a1; s.A64[cr][j0 + 2] = a2;
        s.A64[cr][j0 + 3] = a3; s.A64[cr][j0 + 4] = a4;
    }
    __syncthreads();

    for (int t = tid; t < NTRI; t += 256) {
        int i = 0, rem = t;
        while (rem >= DOUT - i) { rem -= DOUT - i; ++i; }
        int j = i + rem;
        float a = 0.f;
        #pragma unroll 4
        for (int cc = 0; cc < CIN; ++cc)
            a = fmaf(s.Wm[cc][i], s.A64[cc][j], a);
        Ysc[(size_t)b * 400 + j * 20 + i] = a;
        Ysc[(size_t)b * 400 + i * 20 + j] = a;
    }
}

// ================= K2: warp-per-matrix Jacobi, fused col rotation =================
// Round-3 proven math. Col rotation is applied immediately after each pair's
// angle (legal: (J^T A) J = J^T (A J), and pair k's angle inputs live in
// columns P_k,Q_k which only pair k touches). Saves cc/ss arrays -> fewer regs,
// enabling 3 blocks/SM via __launch_bounds__(256, 3).
struct Sched { int p[19][10]; int q[19][10]; };
__host__ __device__ constexpr Sched mksched() {
    Sched s{};
    for (int r = 0; r < 19; ++r)
        for (int k = 0; k < 10; ++k) {
            int a = (k == 0) ? 0 : ((k - 1 + r) % 19) + 1;
            int b = ((18 - k + r) % 19) + 1;
            s.p[r][k] = a < b ? a : b;
            s.q[r][k] = a > b ? a : b;
        }
    return s;
}

__global__ __launch_bounds__(256, 3)
void eig_kernel(const float* __restrict__ lw, const float* __restrict__ lb,
                float* __restrict__ out)
{
    constexpr Sched S = mksched();
    const int w    = threadIdx.x >> 5;
    const int lane = threadIdx.x & 31;
    const int b    = blockIdx.x * 8 + w;

    __shared__ float Usm[8][DOUT][21];
    __shared__ float Vsm[8][DOUT][21];

    float a[DOUT], u[DOUT];
    #pragma unroll
    for (int j = 0; j < DOUT; ++j) {
        a[j] = (lane < DOUT) ? Ysc[(size_t)b * 400 + j * 20 + lane] : 0.f;
        u[j] = (lane == j) ? 1.f : 0.f;
    }

    #pragma unroll 1
    for (int sweep = 0; sweep < NSWEEP; ++sweep) {
        #pragma unroll
        for (int r = 0; r < 19; ++r) {
            float cr = 1.f, tr = 0.f;
            int prt = lane;
            // per pair: angle from pristine columns, then immediate col rotation
            #pragma unroll
            for (int k = 0; k < 10; ++k) {
                const int P = S.p[r][k], Q = S.q[r][k];
                float app = __shfl_sync(0xffffffffu, a[P], P);
                float aqq = __shfl_sync(0xffffffffu, a[Q], Q);
                float apq = __shfl_sync(0xffffffffu, a[Q], P);
                float c1, s1;
                if (fabsf(apq) > 1e-30f) {
                    float th  = 0.5f * (aqq - app) * __frcp_rn(apq);
                    // inf-safe: th huge -> den=inf -> t1=0 -> c=1,s=0
                    float den = fabsf(th) + sqrtf(fmaf(th, th, 1.f));
                    float t1  = copysignf(__frcp_rn(den), th);
                    c1 = rsqrtf(fmaf(t1, t1, 1.f));
                    s1 = t1 * c1;
                } else { c1 = 1.f; s1 = 0.f; }
                if (lane == P) { cr = c1; tr = -s1; prt = Q; }
                if (lane == Q) { cr = c1; tr =  s1; prt = P; }
                // col rotation: A <- A J, U <- U J (lane-local, disjoint columns)
                float ap = a[P], aq = a[Q];
                a[P] = fmaf(c1, ap, -s1 * aq);
                a[Q] = fmaf(s1, ap,  c1 * aq);
                float up = u[P], uq = u[Q];
                u[P] = fmaf(c1, up, -s1 * uq);
                u[Q] = fmaf(s1, up,  c1 * uq);
            }
            // row phase: A <- J^T A (on the col-updated matrix; J^T(AJ) = (J^T A)J)
            #pragma unroll
            for (int j = 0; j < DOUT; ++j) {
                float o = __shfl_sync(0xffffffffu, a[j], prt);
                a[j] = fmaf(cr, a[j], tr * o);
            }
        }
    }

    // eigenvalue of this lane's row = diagonal element
    float lam = 1.f;
    #pragma unroll
    for (int j = 0; j < DOUT; ++j)
        if (lane == j) lam = a[j];
    float ls = logf(fmaxf(lam, 1e-4f));

    // stage U and U*diag(logS) rows to smem
    #pragma unroll
    for (int j = 0; j < DOUT; ++j) {
        float lj = __shfl_sync(0xffffffffu, ls, j);
        if (lane < DOUT) {
            Usm[w][lane][j] = u[j];
            Vsm[w][lane][j] = u[j] * lj;
        }
    }
    __syncwarp();

    // triu(M) entries + linear head partials
    float res[10];
    #pragma unroll
    for (int o = 0; o < 10; ++o) res[o] = 0.f;

    for (int t = lane; t < NTRI; t += 32) {
        int i = 0, rem = t;
        while (rem >= DOUT - i) { rem -= DOUT - i; ++i; }
        int j = i + rem;
        float acc = 0.f;
        #pragma unroll
        for (int m = 0; m < DOUT; ++m)
            acc = fmaf(Vsm[w][i][m], Usm[w][j][m], acc);
        #pragma unroll
        for (int o = 0; o < 10; ++o)
            res[o] = fmaf(acc, lw[o * NTRI + t], res[o]);
    }
    // warp reduction
    #pragma unroll
    for (int o = 0; o < 10; ++o) {
        #pragma unroll
        for (int d = 16; d > 0; d >>= 1)
            res[o] += __shfl_xor_sync(0xffffffffu, res[o], d);
    }
    #pragma unroll
    for (int o = 0; o < 10; ++o)
        if (lane == o) out[(size_t)b * 10 + o] = res[o] + lb[o];
}

// ================= launch =================
extern "C" void kernel_launch(void* const* d_in, const int* in_sizes, int n_in,
                              void* d_out, int out_size) {
    const float* x  = (const float*)d_in[0];
    const float* W  = (const float*)d_in[1];
    const float* lw = (const float*)d_in[2];
    const float* lb = (const float*)d_in[3];
    float* out = (float*)d_out;

    cudaFuncSetAttribute(gram_kernel,
                         cudaFuncAttributeMaxDynamicSharedMemorySize,
                         (int)sizeof(SM1));
    gram_kernel<<<BATCH, 256, sizeof(SM1)>>>(x, W);
    eig_kernel<<<BATCH / 8, 256>>>(lw, lb, out);
}

// round 11
// speedup vs baseline: 1.6783x; 1.2632x over previous
#include <cuda_runtime.h>

#define BATCH 4096
#define CIN   64
#define NF    256
#define DOUT  20
#define NTRI  210
#define NSWEEP 8

// ---------------- scratch: Y matrices, layout Ysc[b*400 + j*20 + i] = Y[i][j]
__device__ float Ysc[BATCH * DOUT * DOUT];

// ================= K1: gram + kernel matrix + Y = W^T K W =================
struct SM1 {
    float xs[128][68];
    float G[CIN][65];
    float Wm[CIN][DOUT];
    float A64[CIN][DOUT];
    float rs[CIN][4];
    float mean[CIN];
    float sq[CIN];
};

__global__ __launch_bounds__(256, 3)
void gram_kernel(const float* __restrict__ x, const float* __restrict__ W)
{
    extern __shared__ char smraw[];
    SM1& s = *reinterpret_cast<SM1*>(smraw);
    const int b   = blockIdx.x;
    const int tid = threadIdx.x;
    const int c   = tid & 63;
    const int s2  = tid >> 6;
    const int ty  = tid >> 4, tx = tid & 15;

    for (int idx = tid; idx < CIN * DOUT; idx += 256)
        (&s.Wm[0][0])[idx] = W[idx];

    float acc[4][4];
    #pragma unroll
    for (int i = 0; i < 4; ++i)
        #pragma unroll
        for (int j = 0; j < 4; ++j) acc[i][j] = 0.f;
    float sumacc = 0.f;

    for (int ch = 0; ch < 2; ++ch) {
        const float* xp = x + ((size_t)b * CIN + c) * NF + ch * 128 + s2 * 32;
        #pragma unroll
        for (int i = 0; i < 8; ++i) {
            float4 v = *reinterpret_cast<const float4*>(xp + 4 * i);
            int n = s2 * 32 + 4 * i;
            s.xs[n + 0][c] = v.x; s.xs[n + 1][c] = v.y;
            s.xs[n + 2][c] = v.z; s.xs[n + 3][c] = v.w;
            sumacc += v.x + v.y + v.z + v.w;
        }
        __syncthreads();
        #pragma unroll 8
        for (int n = 0; n < 128; ++n) {
            float4 af = *reinterpret_cast<const float4*>(&s.xs[n][4 * ty]);
            float4 bf = *reinterpret_cast<const float4*>(&s.xs[n][4 * tx]);
            float av[4] = {af.x, af.y, af.z, af.w};
            float bv[4] = {bf.x, bf.y, bf.z, bf.w};
            #pragma unroll
            for (int i = 0; i < 4; ++i)
                #pragma unroll
                for (int j = 0; j < 4; ++j)
                    acc[i][j] = fmaf(av[i], bv[j], acc[i][j]);
        }
        __syncthreads();
    }

    s.rs[c][s2] = sumacc;
    #pragma unroll
    for (int i = 0; i < 4; ++i)
        #pragma unroll
        for (int j = 0; j < 4; ++j)
            s.G[4 * ty + i][4 * tx + j] = acc[i][j];
    __syncthreads();

    if (tid < CIN) {
        float m = (s.rs[tid][0] + s.rs[tid][1] + s.rs[tid][2] + s.rs[tid][3]) * (1.f / NF);
        s.mean[tid] = m;
        s.sq[tid]   = s.G[tid][tid] - (float)NF * m * m;
    }
    __syncthreads();

    #pragma unroll
    for (int i = 0; i < 4; ++i) {
        int cc = 4 * ty + i;
        float mc = s.mean[cc], sc = s.sq[cc];
        #pragma unroll
        for (int j = 0; j < 4; ++j) {
            int d = 4 * tx + j;
            float g  = s.G[cc][d] - (float)NF * mc * s.mean[d];
            float d2 = fmaxf(sc + s.sq[d] - 2.f * g, 0.f) * (1.f / NF);
            s.G[cc][d] = __expf(-50.f * d2);
        }
    }
    __syncthreads();

    {
        const int cr = tid >> 2;
        const int j0 = (tid & 3) * 5;
        float a0 = 0.f, a1 = 0.f, a2 = 0.f, a3 = 0.f, a4 = 0.f;
        #pragma unroll 4
        for (int d = 0; d < CIN; ++d) {
            float kk = s.G[cr][d];
            a0 = fmaf(kk, s.Wm[d][j0 + 0], a0);
            a1 = fmaf(kk, s.Wm[d][j0 + 1], a1);
            a2 = fmaf(kk, s.Wm[d][j0 + 2], a2);
            a3 = fmaf(kk, s.Wm[d][j0 + 3], a3);
            a4 = fmaf(kk, s.Wm[d][j0 + 4], a4);
        }
        s.A64[cr][j0 + 0] = a0; s.A64[cr][j0 + 1] = a1; s.A64[cr][j0 + 2] = a2;
        s.A64[cr][j0 + 3] = a3; s.A64[cr][j0 + 4] = a4;
    }
    __syncthreads();

    for (int t = tid; t < NTRI; t += 256) {
        int i = 0, rem = t;
        while (rem >= DOUT - i) { rem -= DOUT - i; ++i; }
        int j = i + rem;
        float a = 0.f;
        #pragma unroll 4
        for (int cc = 0; cc < CIN; ++cc)
            a = fmaf(s.Wm[cc][i], s.A64[cc][j], a);
        Ysc[(size_t)b * 400 + j * 20 + i] = a;
        Ysc[(size_t)b * 400 + i * 20 + j] = a;
    }
}

// ================= K2: warp-per-matrix Jacobi, fused col rotation =================
struct Sched { int p[19][10]; int q[19][10]; };
__host__ __device__ constexpr Sched mksched() {
    Sched s{};
    for (int r = 0; r < 19; ++r)
        for (int k = 0; k < 10; ++k) {
            int a = (k == 0) ? 0 : ((k - 1 + r) % 19) + 1;
            int b = ((18 - k + r) % 19) + 1;
            s.p[r][k] = a < b ? a : b;
            s.q[r][k] = a > b ? a : b;
        }
    return s;
}

__global__ __launch_bounds__(256, 3)
void eig_kernel(const float* __restrict__ lw, const float* __restrict__ lb,
                float* __restrict__ out)
{
    constexpr Sched S = mksched();
    const int w    = threadIdx.x >> 5;
    const int lane = threadIdx.x & 31;
    const int b    = blockIdx.x * 8 + w;

    __shared__ float Usm[8][DOUT][21];
    __shared__ float Vsm[8][DOUT][21];

    float a[DOUT], u[DOUT];
    #pragma unroll
    for (int j = 0; j < DOUT; ++j) {
        a[j] = (lane < DOUT) ? Ysc[(size_t)b * 400 + j * 20 + lane] : 0.f;
        u[j] = (lane == j) ? 1.f : 0.f;
    }

    #pragma unroll 1
    for (int sweep = 0; sweep < NSWEEP; ++sweep) {
        #pragma unroll
        for (int r = 0; r < 19; ++r) {
            float cr = 1.f, tr = 0.f;
            int prt = lane;
            // per pair: angle from pristine columns, then immediate col rotation
            #pragma unroll
            for (int k = 0; k < 10; ++k) {
                const int P = S.p[r][k], Q = S.q[r][k];
                float app = __shfl_sync(0xffffffffu, a[P], P);
                float aqq = __shfl_sync(0xffffffffu, a[Q], Q);
                float apq = __shfl_sync(0xffffffffu, a[Q], P);
                float c1, s1;
                if (fabsf(apq) > 1e-30f) {
                    float th  = 0.5f * (aqq - app) * __frcp_rn(apq);
                    // inf-safe: th huge -> den=inf -> t1=0 -> c=1,s=0
                    float den = fabsf(th) + sqrtf(fmaf(th, th, 1.f));
                    float t1  = copysignf(__frcp_rn(den), th);
                    c1 = rsqrtf(fmaf(t1, t1, 1.f));
                    s1 = t1 * c1;
                } else { c1 = 1.f; s1 = 0.f; }
                if (lane == P) { cr = c1; tr = -s1; prt = Q; }
                if (lane == Q) { cr = c1; tr =  s1; prt = P; }
                // col rotation: A <- A J, U <- U J (lane-local, disjoint columns)
                float ap = a[P], aq = a[Q];
                a[P] = fmaf(c1, ap, -s1 * aq);
                a[Q] = fmaf(s1, ap,  c1 * aq);
                float up = u[P], uq = u[Q];
                u[P] = fmaf(c1, up, -s1 * uq);
                u[Q] = fmaf(s1, up,  c1 * uq);
            }
            // row phase: A <- J^T A (on the col-updated matrix; J^T(AJ) = (J^T A)J)
            #pragma unroll
            for (int j = 0; j < DOUT; ++j) {
                float o = __shfl_sync(0xffffffffu, a[j], prt);
                a[j] = fmaf(cr, a[j], tr * o);
            }
        }
    }

    // eigenvalue of this lane's row = diagonal element
    float lam = 1.f;
    #pragma unroll
    for (int j = 0; j < DOUT; ++j)
        if (lane == j) lam = a[j];
    float ls = logf(fmaxf(lam, 1e-4f));

    // stage U and U*diag(logS) rows to smem
    #pragma unroll
    for (int j = 0; j < DOUT; ++j) {
        float lj = __shfl_sync(0xffffffffu, ls, j);
        if (lane < DOUT) {
            Usm[w][lane][j] = u[j];
            Vsm[w][lane][j] = u[j] * lj;
        }
    }
    __syncwarp();

    // triu(M) entries + linear head partials
    float res[10];
    #pragma unroll
    for (int o = 0; o < 10; ++o) res[o] = 0.f;

    for (int t = lane; t < NTRI; t += 32) {
        int i = 0, rem = t;
        while (rem >= DOUT - i) { rem -= DOUT - i; ++i; }
        int j = i + rem;
        float acc = 0.f;
        #pragma unroll
        for (int m = 0; m < DOUT; ++m)
            acc = fmaf(Vsm[w][i][m], Usm[w][j][m], acc);
        #pragma unroll
        for (int o = 0; o < 10; ++o)
            res[o] = fmaf(acc, lw[o * NTRI + t], res[o]);
    }
    // warp reduction
    #pragma unroll
    for (int o = 0; o < 10; ++o) {
        #pragma unroll
        for (int d = 16; d > 0; d >>= 1)
            res[o] += __shfl_xor_sync(0xffffffffu, res[o], d);
    }
    #pragma unroll
    for (int o = 0; o < 10; ++o)
        if (lane == o) out[(size_t)b * 10 + o] = res[o] + lb[o];
}

// ================= launch =================
extern "C" void kernel_launch(void* const* d_in, const int* in_sizes, int n_in,
                              void* d_out, int out_size) {
    const float* x  = (const float*)d_in[0];
    const float* W  = (const float*)d_in[1];
    const float* lw = (const float*)d_in[2];
    const float* lb = (const float*)d_in[3];
    float* out = (float*)d_out;

    cudaFuncSetAttribute(gram_kernel,
                         cudaFuncAttributeMaxDynamicSharedMemorySize,
                         (int)sizeof(SM1));
    gram_kernel<<<BATCH, 256, sizeof(SM1)>>>(x, W);
    eig_kernel<<<BATCH / 8, 256>>>(lw, lb, out);
}

// round 12
// speedup vs baseline: 2.1820x; 1.3001x over previous
#include <cuda_runtime.h>

#define BATCH 4096
#define CIN   64
#define NF    256
#define DOUT  20
#define NTRI  210
#define NSWEEP 6

// ---------------- scratch: Y matrices, layout Ysc[b*400 + j*20 + i] = Y[i][j]
__device__ float Ysc[BATCH * DOUT * DOUT];

// ================= K1: gram + kernel matrix + Y = W^T K W =================
struct SM1 {
    float xs[128][68];
    float G[CIN][65];
    float Wm[CIN][DOUT];
    float A64[CIN][DOUT];
    float rs[CIN][4];
    float mean[CIN];
    float sq[CIN];
};

__global__ __launch_bounds__(256, 3)
void gram_kernel(const float* __restrict__ x, const float* __restrict__ W)
{
    extern __shared__ char smraw[];
    SM1& s = *reinterpret_cast<SM1*>(smraw);
    const int b   = blockIdx.x;
    const int tid = threadIdx.x;
    const int c   = tid & 63;
    const int s2  = tid >> 6;
    const int ty  = tid >> 4, tx = tid & 15;

    for (int idx = tid; idx < CIN * DOUT; idx += 256)
        (&s.Wm[0][0])[idx] = W[idx];

    float acc[4][4];
    #pragma unroll
    for (int i = 0; i < 4; ++i)
        #pragma unroll
        for (int j = 0; j < 4; ++j) acc[i][j] = 0.f;
    float sumacc = 0.f;

    for (int ch = 0; ch < 2; ++ch) {
        const float* xp = x + ((size_t)b * CIN + c) * NF + ch * 128 + s2 * 32;
        #pragma unroll
        for (int i = 0; i < 8; ++i) {
            float4 v = *reinterpret_cast<const float4*>(xp + 4 * i);
            int n = s2 * 32 + 4 * i;
            s.xs[n + 0][c] = v.x; s.xs[n + 1][c] = v.y;
            s.xs[n + 2][c] = v.z; s.xs[n + 3][c] = v.w;
            sumacc += v.x + v.y + v.z + v.w;
        }
        __syncthreads();
        #pragma unroll 8
        for (int n = 0; n < 128; ++n) {
            float4 af = *reinterpret_cast<const float4*>(&s.xs[n][4 * ty]);
            float4 bf = *reinterpret_cast<const float4*>(&s.xs[n][4 * tx]);
            float av[4] = {af.x, af.y, af.z, af.w};
            float bv[4] = {bf.x, bf.y, bf.z, bf.w};
            #pragma unroll
            for (int i = 0; i < 4; ++i)
                #pragma unroll
                for (int j = 0; j < 4; ++j)
                    acc[i][j] = fmaf(av[i], bv[j], acc[i][j]);
        }
        __syncthreads();
    }

    s.rs[c][s2] = sumacc;
    #pragma unroll
    for (int i = 0; i < 4; ++i)
        #pragma unroll
        for (int j = 0; j < 4; ++j)
            s.G[4 * ty + i][4 * tx + j] = acc[i][j];
    __syncthreads();

    if (tid < CIN) {
        float m = (s.rs[tid][0] + s.rs[tid][1] + s.rs[tid][2] + s.rs[tid][3]) * (1.f / NF);
        s.mean[tid] = m;
        s.sq[tid]   = s.G[tid][tid] - (float)NF * m * m;
    }
    __syncthreads();

    #pragma unroll
    for (int i = 0; i < 4; ++i) {
        int cc = 4 * ty + i;
        float mc = s.mean[cc], sc = s.sq[cc];
        #pragma unroll
        for (int j = 0; j < 4; ++j) {
            int d = 4 * tx + j;
            float g  = s.G[cc][d] - (float)NF * mc * s.mean[d];
            float d2 = fmaxf(sc + s.sq[d] - 2.f * g, 0.f) * (1.f / NF);
            s.G[cc][d] = __expf(-50.f * d2);
        }
    }
    __syncthreads();

    {
        const int cr = tid >> 2;
        const int j0 = (tid & 3) * 5;
        float a0 = 0.f, a1 = 0.f, a2 = 0.f, a3 = 0.f, a4 = 0.f;
        #pragma unroll 4
        for (int d = 0; d < CIN; ++d) {
            float kk = s.G[cr][d];
            a0 = fmaf(kk, s.Wm[d][j0 + 0], a0);
            a1 = fmaf(kk, s.Wm[d][j0 + 1], a1);
            a2 = fmaf(kk, s.Wm[d][j0 + 2], a2);
            a3 = fmaf(kk, s.Wm[d][j0 + 3], a3);
            a4 = fmaf(kk, s.Wm[d][j0 + 4], a4);
        }
        s.A64[cr][j0 + 0] = a0; s.A64[cr][j0 + 1] = a1; s.A64[cr][j0 + 2] = a2;
        s.A64[cr][j0 + 3] = a3; s.A64[cr][j0 + 4] = a4;
    }
    __syncthreads();

    for (int t = tid; t < NTRI; t += 256) {
        int i = 0, rem = t;
        while (rem >= DOUT - i) { rem -= DOUT - i; ++i; }
        int j = i + rem;
        float a = 0.f;
        #pragma unroll 4
        for (int cc = 0; cc < CIN; ++cc)
            a = fmaf(s.Wm[cc][i], s.A64[cc][j], a);
        Ysc[(size_t)b * 400 + j * 20 + i] = a;
        Ysc[(size_t)b * 400 + i * 20 + j] = a;
    }
}

// ================= K2: warp-per-matrix Jacobi, fused col rotation =================
struct Sched { int p[19][10]; int q[19][10]; };
__host__ __device__ constexpr Sched mksched() {
    Sched s{};
    for (int r = 0; r < 19; ++r)
        for (int k = 0; k < 10; ++k) {
            int a = (k == 0) ? 0 : ((k - 1 + r) % 19) + 1;
            int b = ((18 - k + r) % 19) + 1;
            s.p[r][k] = a < b ? a : b;
            s.q[r][k] = a > b ? a : b;
        }
    return s;
}

__global__ __launch_bounds__(256, 3)
void eig_kernel(const float* __restrict__ lw, const float* __restrict__ lb,
                float* __restrict__ out)
{
    constexpr Sched S = mksched();
    const int w    = threadIdx.x >> 5;
    const int lane = threadIdx.x & 31;
    const int b    = blockIdx.x * 8 + w;

    __shared__ float Usm[8][DOUT][21];
    __shared__ float Vsm[8][DOUT][21];

    float a[DOUT], u[DOUT];
    #pragma unroll
    for (int j = 0; j < DOUT; ++j) {
        a[j] = (lane < DOUT) ? Ysc[(size_t)b * 400 + j * 20 + lane] : 0.f;
        u[j] = (lane == j) ? 1.f : 0.f;
    }

    #pragma unroll 1
    for (int sweep = 0; sweep < NSWEEP; ++sweep) {
        #pragma unroll
        for (int r = 0; r < 19; ++r) {
            float cr = 1.f, tr = 0.f;
            int prt = lane;
            // per pair: angle from pristine columns, then immediate col rotation
            #pragma unroll
            for (int k = 0; k < 10; ++k) {
                const int P = S.p[r][k], Q = S.q[r][k];
                float app = __shfl_sync(0xffffffffu, a[P], P);
                float aqq = __shfl_sync(0xffffffffu, a[Q], Q);
                float apq = __shfl_sync(0xffffffffu, a[Q], P);
                float c1, s1;
                if (fabsf(apq) > 1e-30f) {
                    float th  = 0.5f * (aqq - app) * __frcp_rn(apq);
                    // inf-safe: th huge -> den=inf -> t1=0 -> c=1,s=0
                    float den = fabsf(th) + sqrtf(fmaf(th, th, 1.f));
                    float t1  = copysignf(__frcp_rn(den), th);
                    c1 = rsqrtf(fmaf(t1, t1, 1.f));
                    s1 = t1 * c1;
                } else { c1 = 1.f; s1 = 0.f; }
                if (lane == P) { cr = c1; tr = -s1; prt = Q; }
                if (lane == Q) { cr = c1; tr =  s1; prt = P; }
                // col rotation: A <- A J, U <- U J (lane-local, disjoint columns)
                float ap = a[P], aq = a[Q];
                a[P] = fmaf(c1, ap, -s1 * aq);
                a[Q] = fmaf(s1, ap,  c1 * aq);
                float up = u[P], uq = u[Q];
                u[P] = fmaf(c1, up, -s1 * uq);
                u[Q] = fmaf(s1, up,  c1 * uq);
            }
            // row phase: A <- J^T A (on the col-updated matrix; J^T(AJ) = (J^T A)J)
            #pragma unroll
            for (int j = 0; j < DOUT; ++j) {
                float o = __shfl_sync(0xffffffffu, a[j], prt);
                a[j] = fmaf(cr, a[j], tr * o);
            }
        }
    }

    // eigenvalue of this lane's row = diagonal element
    float lam = 1.f;
    #pragma unroll
    for (int j = 0; j < DOUT; ++j)
        if (lane == j) lam = a[j];
    float ls = logf(fmaxf(lam, 1e-4f));

    // stage U and U*diag(logS) rows to smem
    #pragma unroll
    for (int j = 0; j < DOUT; ++j) {
        float lj = __shfl_sync(0xffffffffu, ls, j);
        if (lane < DOUT) {
            Usm[w][lane][j] = u[j];
            Vsm[w][lane][j] = u[j] * lj;
        }
    }
    __syncwarp();

    // triu(M) entries + linear head partials
    float res[10];
    #pragma unroll
    for (int o = 0; o < 10; ++o) res[o] = 0.f;

    for (int t = lane; t < NTRI; t += 32) {
        int i = 0, rem = t;
        while (rem >= DOUT - i) { rem -= DOUT - i; ++i; }
        int j = i + rem;
        float acc = 0.f;
        #pragma unroll
        for (int m = 0; m < DOUT; ++m)
            acc = fmaf(Vsm[w][i][m], Usm[w][j][m], acc);
        #pragma unroll
        for (int o = 0; o < 10; ++o)
            res[o] = fmaf(acc, lw[o * NTRI + t], res[o]);
    }
    // warp reduction
    #pragma unroll
    for (int o = 0; o < 10; ++o) {
        #pragma unroll
        for (int d = 16; d > 0; d >>= 1)
            res[o] += __shfl_xor_sync(0xffffffffu, res[o], d);
    }
    #pragma unroll
    for (int o = 0; o < 10; ++o)
        if (lane == o) out[(size_t)b * 10 + o] = res[o] + lb[o];
}

// ================= launch =================
extern "C" void kernel_launch(void* const* d_in, const int* in_sizes, int n_in,
                              void* d_out, int out_size) {
    const float* x  = (const float*)d_in[0];
    const float* W  = (const float*)d_in[1];
    const float* lw = (const float*)d_in[2];
    const float* lb = (const float*)d_in[3];
    float* out = (float*)d_out;

    cudaFuncSetAttribute(gram_kernel,
                         cudaFuncAttributeMaxDynamicSharedMemorySize,
                         (int)sizeof(SM1));
    gram_kernel<<<BATCH, 256, sizeof(SM1)>>>(x, W);
    eig_kernel<<<BATCH / 8, 256>>>(lw, lb, out);
}

// round 13
// speedup vs baseline: 2.1861x; 1.0019x over previous
#include <cuda_runtime.h>

#define BATCH 4096
#define CIN   64
#define NF    256
#define DOUT  20
#define NTRI  210
#define NSWEEP 6

// ---------------- scratch: Y matrices, layout Ysc[b*400 + j*20 + i] = Y[i][j]
__device__ float Ysc[BATCH * DOUT * DOUT];

// ================= K1: gram + kernel matrix + Y = W^T K W =================
struct SM1 {
    float xs[128][68];
    float G[CIN][65];
    float Wm[CIN][DOUT];
    float A64[CIN][DOUT];
    float rs[CIN][4];
    float mean[CIN];
    float sq[CIN];
};

__global__ __launch_bounds__(256, 3)
void gram_kernel(const float* __restrict__ x, const float* __restrict__ W)
{
    extern __shared__ char smraw[];
    SM1& s = *reinterpret_cast<SM1*>(smraw);
    const int b   = blockIdx.x;
    const int tid = threadIdx.x;
    const int c   = tid & 63;
    const int s2  = tid >> 6;
    // gram tiling: 128 active threads, 4 rows x 8 cols each (warps 0-3, one per SMSP)
    const bool gact = tid < 128;
    const int ty  = tid >> 3;          // 0..15 (row tile of 4)
    const int tx  = tid & 7;           // 0..7  (col tile of 8)

    for (int idx = tid; idx < CIN * DOUT; idx += 256)
        (&s.Wm[0][0])[idx] = W[idx];

    float acc[4][8];
    #pragma unroll
    for (int i = 0; i < 4; ++i)
        #pragma unroll
        for (int j = 0; j < 8; ++j) acc[i][j] = 0.f;
    float sumacc = 0.f;

    for (int ch = 0; ch < 2; ++ch) {
        const float* xp = x + ((size_t)b * CIN + c) * NF + ch * 128 + s2 * 32;
        #pragma unroll
        for (int i = 0; i < 8; ++i) {
            float4 v = *reinterpret_cast<const float4*>(xp + 4 * i);
            int n = s2 * 32 + 4 * i;
            s.xs[n + 0][c] = v.x; s.xs[n + 1][c] = v.y;
            s.xs[n + 2][c] = v.z; s.xs[n + 3][c] = v.w;
            sumacc += v.x + v.y + v.z + v.w;
        }
        __syncthreads();
        if (gact) {
            #pragma unroll 8
            for (int n = 0; n < 128; ++n) {
                float4 af = *reinterpret_cast<const float4*>(&s.xs[n][4 * ty]);
                float4 b0 = *reinterpret_cast<const float4*>(&s.xs[n][8 * tx]);
                float4 b1 = *reinterpret_cast<const float4*>(&s.xs[n][8 * tx + 4]);
                float av[4] = {af.x, af.y, af.z, af.w};
                float bv[8] = {b0.x, b0.y, b0.z, b0.w, b1.x, b1.y, b1.z, b1.w};
                #pragma unroll
                for (int i = 0; i < 4; ++i)
                    #pragma unroll
                    for (int j = 0; j < 8; ++j)
                        acc[i][j] = fmaf(av[i], bv[j], acc[i][j]);
            }
        }
        __syncthreads();
    }

    s.rs[c][s2] = sumacc;
    if (gact) {
        #pragma unroll
        for (int i = 0; i < 4; ++i)
            #pragma unroll
            for (int j = 0; j < 8; ++j)
                s.G[4 * ty + i][8 * tx + j] = acc[i][j];
    }
    __syncthreads();

    if (tid < CIN) {
        float m = (s.rs[tid][0] + s.rs[tid][1] + s.rs[tid][2] + s.rs[tid][3]) * (1.f / NF);
        s.mean[tid] = m;
        s.sq[tid]   = s.G[tid][tid] - (float)NF * m * m;
    }
    __syncthreads();

    if (gact) {
        #pragma unroll
        for (int i = 0; i < 4; ++i) {
            int cc = 4 * ty + i;
            float mc = s.mean[cc], sc = s.sq[cc];
            #pragma unroll
            for (int j = 0; j < 8; ++j) {
                int d = 8 * tx + j;
                float g  = s.G[cc][d] - (float)NF * mc * s.mean[d];
                float d2 = fmaxf(sc + s.sq[d] - 2.f * g, 0.f) * (1.f / NF);
                s.G[cc][d] = __expf(-50.f * d2);
            }
        }
    }
    __syncthreads();

    {
        const int cr = tid >> 2;
        const int j0 = (tid & 3) * 5;
        float a0 = 0.f, a1 = 0.f, a2 = 0.f, a3 = 0.f, a4 = 0.f;
        #pragma unroll 4
        for (int d = 0; d < CIN; ++d) {
            float kk = s.G[cr][d];
            a0 = fmaf(kk, s.Wm[d][j0 + 0], a0);
            a1 = fmaf(kk, s.Wm[d][j0 + 1], a1);
            a2 = fmaf(kk, s.Wm[d][j0 + 2], a2);
            a3 = fmaf(kk, s.Wm[d][j0 + 3], a3);
            a4 = fmaf(kk, s.Wm[d][j0 + 4], a4);
        }
        s.A64[cr][j0 + 0] = a0; s.A64[cr][j0 + 1] = a1; s.A64[cr][j0 + 2] = a2;
        s.A64[cr][j0 + 3] = a3; s.A64[cr][j0 + 4] = a4;
    }
    __syncthreads();

    for (int t = tid; t < NTRI; t += 256) {
        int i = 0, rem = t;
        while (rem >= DOUT - i) { rem -= DOUT - i; ++i; }
        int j = i + rem;
        float a = 0.f;
        #pragma unroll 4
        for (int cc = 0; cc < CIN; ++cc)
            a = fmaf(s.Wm[cc][i], s.A64[cc][j], a);
        Ysc[(size_t)b * 400 + j * 20 + i] = a;
        Ysc[(size_t)b * 400 + i * 20 + j] = a;
    }
}

// ================= K2: warp-per-matrix Jacobi, fused col rotation =================
struct Sched { int p[19][10]; int q[19][10]; };
__host__ __device__ constexpr Sched mksched() {
    Sched s{};
    for (int r = 0; r < 19; ++r)
        for (int k = 0; k < 10; ++k) {
            int a = (k == 0) ? 0 : ((k - 1 + r) % 19) + 1;
            int b = ((18 - k + r) % 19) + 1;
            s.p[r][k] = a < b ? a : b;
            s.q[r][k] = a > b ? a : b;
        }
    return s;
}

__global__ __launch_bounds__(256, 4)
void eig_kernel(const float* __restrict__ lw, const float* __restrict__ lb,
                float* __restrict__ out)
{
    constexpr Sched S = mksched();
    const int w    = threadIdx.x >> 5;
    const int lane = threadIdx.x & 31;
    const int b    = blockIdx.x * 8 + w;

    __shared__ float Usm[8][DOUT][21];
    __shared__ float Vsm[8][DOUT][21];

    float a[DOUT], u[DOUT];
    #pragma unroll
    for (int j = 0; j < DOUT; ++j) {
        a[j] = (lane < DOUT) ? Ysc[(size_t)b * 400 + j * 20 + lane] : 0.f;
        u[j] = (lane == j) ? 1.f : 0.f;
    }

    #pragma unroll 1
    for (int sweep = 0; sweep < NSWEEP; ++sweep) {
        #pragma unroll
        for (int r = 0; r < 19; ++r) {
            float cr = 1.f, tr = 0.f;
            int prt = lane;
            // per pair: angle from pristine columns, then immediate col rotation
            #pragma unroll
            for (int k = 0; k < 10; ++k) {
                const int P = S.p[r][k], Q = S.q[r][k];
                float app = __shfl_sync(0xffffffffu, a[P], P);
                float aqq = __shfl_sync(0xffffffffu, a[Q], Q);
                float apq = __shfl_sync(0xffffffffu, a[Q], P);
                float c1, s1;
                if (fabsf(apq) > 1e-30f) {
                    float th  = 0.5f * (aqq - app) * __frcp_rn(apq);
                    // inf-safe: th huge -> den=inf -> t1=0 -> c=1,s=0
                    float den = fabsf(th) + sqrtf(fmaf(th, th, 1.f));
                    float t1  = copysignf(__frcp_rn(den), th);
                    c1 = rsqrtf(fmaf(t1, t1, 1.f));
                    s1 = t1 * c1;
                } else { c1 = 1.f; s1 = 0.f; }
                if (lane == P) { cr = c1; tr = -s1; prt = Q; }
                if (lane == Q) { cr = c1; tr =  s1; prt = P; }
                // col rotation: A <- A J, U <- U J (lane-local, disjoint columns)
                float ap = a[P], aq = a[Q];
                a[P] = fmaf(c1, ap, -s1 * aq);
                a[Q] = fmaf(s1, ap,  c1 * aq);
                float up = u[P], uq = u[Q];
                u[P] = fmaf(c1, up, -s1 * uq);
                u[Q] = fmaf(s1, up,  c1 * uq);
            }
            // row phase: A <- J^T A (on the col-updated matrix; J^T(AJ) = (J^T A)J)
            #pragma unroll
            for (int j = 0; j < DOUT; ++j) {
                float o = __shfl_sync(0xffffffffu, a[j], prt);
                a[j] = fmaf(cr, a[j], tr * o);
            }
        }
    }

    // eigenvalue of this lane's row = diagonal element
    float lam = 1.f;
    #pragma unroll
    for (int j = 0; j < DOUT; ++j)
        if (lane == j) lam = a[j];
    float ls = logf(fmaxf(lam, 1e-4f));

    // stage U and U*diag(logS) rows to smem
    #pragma unroll
    for (int j = 0; j < DOUT; ++j) {
        float lj = __shfl_sync(0xffffffffu, ls, j);
        if (lane < DOUT) {
            Usm[w][lane][j] = u[j];
            Vsm[w][lane][j] = u[j] * lj;
        }
    }
    __syncwarp();

    // triu(M) entries + linear head partials
    float res[10];
    #pragma unroll
    for (int o = 0; o < 10; ++o) res[o] = 0.f;

    for (int t = lane; t < NTRI; t += 32) {
        int i = 0, rem = t;
        while (rem >= DOUT - i) { rem -= DOUT - i; ++i; }
        int j = i + rem;
        float acc = 0.f;
        #pragma unroll
        for (int m = 0; m < DOUT; ++m)
            acc = fmaf(Vsm[w][i][m], Usm[w][j][m], acc);
        #pragma unroll
        for (int o = 0; o < 10; ++o)
            res[o] = fmaf(acc, lw[o * NTRI + t], res[o]);
    }
    // warp reduction
    #pragma unroll
    for (int o = 0; o < 10; ++o) {
        #pragma unroll
        for (int d = 16; d > 0; d >>= 1)
            res[o] += __shfl_xor_sync(0xffffffffu, res[o], d);
    }
    #pragma unroll
    for (int o = 0; o < 10; ++o)
        if (lane == o) out[(size_t)b * 10 + o] = res[o] + lb[o];
}

// ================= launch =================
extern "C" void kernel_launch(void* const* d_in, const int* in_sizes, int n_in,
                              void* d_out, int out_size) {
    const float* x  = (const float*)d_in[0];
    const float* W  = (const float*)d_in[1];
    const float* lw = (const float*)d_in[2];
    const float* lb = (const float*)d_in[3];
    float* out = (float*)d_out;

    cudaFuncSetAttribute(gram_kernel,
                         cudaFuncAttributeMaxDynamicSharedMemorySize,
                         (int)sizeof(SM1));
    gram_kernel<<<BATCH, 256, sizeof(SM1)>>>(x, W);
    eig_kernel<<<BATCH / 8, 256>>>(lw, lb, out);
}

// round 14
// speedup vs baseline: 2.2519x; 1.0301x over previous
#include <cuda_runtime.h>

#define BATCH 4096
#define CIN   64
#define NF    256
#define DOUT  20
#define NTRI  210
#define NSWEEP 6

// ---------------- scratch: Y matrices, layout Ysc[b*400 + j*20 + i] = Y[i][j]
__device__ float Ysc[BATCH * DOUT * DOUT];

// ================= K1: gram + kernel matrix + Y = W^T K W =================
struct SM1 {
    float xs[128][68];
    float G[CIN][65];
    float Wm[CIN][DOUT];
    float A64[CIN][DOUT];
    float rs[CIN][4];
    float mean[CIN];
    float sq[CIN];
};

__global__ __launch_bounds__(256, 3)
void gram_kernel(const float* __restrict__ x, const float* __restrict__ W)
{
    extern __shared__ char smraw[];
    SM1& s = *reinterpret_cast<SM1*>(smraw);
    const int b   = blockIdx.x;
    const int tid = threadIdx.x;
    const int c   = tid & 63;
    const int s2  = tid >> 6;
    const int ty  = tid >> 4, tx = tid & 15;

    for (int idx = tid; idx < CIN * DOUT; idx += 256)
        (&s.Wm[0][0])[idx] = W[idx];

    float acc[4][4];
    #pragma unroll
    for (int i = 0; i < 4; ++i)
        #pragma unroll
        for (int j = 0; j < 4; ++j) acc[i][j] = 0.f;
    float sumacc = 0.f;

    for (int ch = 0; ch < 2; ++ch) {
        const float* xp = x + ((size_t)b * CIN + c) * NF + ch * 128 + s2 * 32;
        #pragma unroll
        for (int i = 0; i < 8; ++i) {
            float4 v = *reinterpret_cast<const float4*>(xp + 4 * i);
            int n = s2 * 32 + 4 * i;
            s.xs[n + 0][c] = v.x; s.xs[n + 1][c] = v.y;
            s.xs[n + 2][c] = v.z; s.xs[n + 3][c] = v.w;
            sumacc += v.x + v.y + v.z + v.w;
        }
        __syncthreads();
        #pragma unroll 8
        for (int n = 0; n < 128; ++n) {
            float4 af = *reinterpret_cast<const float4*>(&s.xs[n][4 * ty]);
            float4 bf = *reinterpret_cast<const float4*>(&s.xs[n][4 * tx]);
            float av[4] = {af.x, af.y, af.z, af.w};
            float bv[4] = {bf.x, bf.y, bf.z, bf.w};
            #pragma unroll
            for (int i = 0; i < 4; ++i)
                #pragma unroll
                for (int j = 0; j < 4; ++j)
                    acc[i][j] = fmaf(av[i], bv[j], acc[i][j]);
        }
        __syncthreads();
    }

    s.rs[c][s2] = sumacc;
    #pragma unroll
    for (int i = 0; i < 4; ++i)
        #pragma unroll
        for (int j = 0; j < 4; ++j)
            s.G[4 * ty + i][4 * tx + j] = acc[i][j];
    __syncthreads();

    if (tid < CIN) {
        float m = (s.rs[tid][0] + s.rs[tid][1] + s.rs[tid][2] + s.rs[tid][3]) * (1.f / NF);
        s.mean[tid] = m;
        s.sq[tid]   = s.G[tid][tid] - (float)NF * m * m;
    }
    __syncthreads();

    #pragma unroll
    for (int i = 0; i < 4; ++i) {
        int cc = 4 * ty + i;
        float mc = s.mean[cc], sc = s.sq[cc];
        #pragma unroll
        for (int j = 0; j < 4; ++j) {
            int d = 4 * tx + j;
            float g  = s.G[cc][d] - (float)NF * mc * s.mean[d];
            float d2 = fmaxf(sc + s.sq[d] - 2.f * g, 0.f) * (1.f / NF);
            s.G[cc][d] = __expf(-50.f * d2);
        }
    }
    __syncthreads();

    {
        const int cr = tid >> 2;
        const int j0 = (tid & 3) * 5;
        float a0 = 0.f, a1 = 0.f, a2 = 0.f, a3 = 0.f, a4 = 0.f;
        #pragma unroll 4
        for (int d = 0; d < CIN; ++d) {
            float kk = s.G[cr][d];
            a0 = fmaf(kk, s.Wm[d][j0 + 0], a0);
            a1 = fmaf(kk, s.Wm[d][j0 + 1], a1);
            a2 = fmaf(kk, s.Wm[d][j0 + 2], a2);
            a3 = fmaf(kk, s.Wm[d][j0 + 3], a3);
            a4 = fmaf(kk, s.Wm[d][j0 + 4], a4);
        }
        s.A64[cr][j0 + 0] = a0; s.A64[cr][j0 + 1] = a1; s.A64[cr][j0 + 2] = a2;
        s.A64[cr][j0 + 3] = a3; s.A64[cr][j0 + 4] = a4;
    }
    __syncthreads();

    for (int t = tid; t < NTRI; t += 256) {
        int i = 0, rem = t;
        while (rem >= DOUT - i) { rem -= DOUT - i; ++i; }
        int j = i + rem;
        float a = 0.f;
        #pragma unroll 4
        for (int cc = 0; cc < CIN; ++cc)
            a = fmaf(s.Wm[cc][i], s.A64[cc][j], a);
        Ysc[(size_t)b * 400 + j * 20 + i] = a;
        Ysc[(size_t)b * 400 + i * 20 + j] = a;
    }
}

// ================= K2: warp-per-matrix Jacobi, fused col rotation =================
struct Sched { int p[19][10]; int q[19][10]; };
__host__ __device__ constexpr Sched mksched() {
    Sched s{};
    for (int r = 0; r < 19; ++r)
        for (int k = 0; k < 10; ++k) {
            int a = (k == 0) ? 0 : ((k - 1 + r) % 19) + 1;
            int b = ((18 - k + r) % 19) + 1;
            s.p[r][k] = a < b ? a : b;
            s.q[r][k] = a > b ? a : b;
        }
    return s;
}

__global__ __launch_bounds__(256, 4)
void eig_kernel(const float* __restrict__ lw, const float* __restrict__ lb,
                float* __restrict__ out)
{
    constexpr Sched S = mksched();
    const int w    = threadIdx.x >> 5;
    const int lane = threadIdx.x & 31;
    const int b    = blockIdx.x * 8 + w;

    __shared__ float Usm[8][DOUT][21];
    __shared__ float Vsm[8][DOUT][21];

    float a[DOUT], u[DOUT];
    #pragma unroll
    for (int j = 0; j < DOUT; ++j) {
        a[j] = (lane < DOUT) ? Ysc[(size_t)b * 400 + j * 20 + lane] : 0.f;
        u[j] = (lane == j) ? 1.f : 0.f;
    }

    #pragma unroll 1
    for (int sweep = 0; sweep < NSWEEP; ++sweep) {
        #pragma unroll
        for (int r = 0; r < 19; ++r) {
            float cr = 1.f, tr = 0.f;
            int prt = lane;
            // per pair: angle from pristine columns, then immediate col rotation
            #pragma unroll
            for (int k = 0; k < 10; ++k) {
                const int P = S.p[r][k], Q = S.q[r][k];
                float app = __shfl_sync(0xffffffffu, a[P], P);
                float aqq = __shfl_sync(0xffffffffu, a[Q], Q);
                float apq = __shfl_sync(0xffffffffu, a[Q], P);
                float c1, s1;
                if (fabsf(apq) > 1e-30f) {
                    float th  = 0.5f * (aqq - app) * __frcp_rn(apq);
                    // inf-safe: th huge -> den=inf -> t1=0 -> c=1,s=0
                    float den = fabsf(th) + sqrtf(fmaf(th, th, 1.f));
                    float t1  = copysignf(__frcp_rn(den), th);
                    c1 = rsqrtf(fmaf(t1, t1, 1.f));
                    s1 = t1 * c1;
                } else { c1 = 1.f; s1 = 0.f; }
                if (lane == P) { cr = c1; tr = -s1; prt = Q; }
                if (lane == Q) { cr = c1; tr =  s1; prt = P; }
                // col rotation: A <- A J, U <- U J (lane-local, disjoint columns)
                float ap = a[P], aq = a[Q];
                a[P] = fmaf(c1, ap, -s1 * aq);
                a[Q] = fmaf(s1, ap,  c1 * aq);
                float up = u[P], uq = u[Q];
                u[P] = fmaf(c1, up, -s1 * uq);
                u[Q] = fmaf(s1, up,  c1 * uq);
            }
            // row phase: A <- J^T A (on the col-updated matrix; J^T(AJ) = (J^T A)J)
            #pragma unroll
            for (int j = 0; j < DOUT; ++j) {
                float o = __shfl_sync(0xffffffffu, a[j], prt);
                a[j] = fmaf(cr, a[j], tr * o);
            }
        }
    }

    // eigenvalue of this lane's row = diagonal element
    float lam = 1.f;
    #pragma unroll
    for (int j = 0; j < DOUT; ++j)
        if (lane == j) lam = a[j];
    float ls = logf(fmaxf(lam, 1e-4f));

    // stage U and U*diag(logS) rows to smem
    #pragma unroll
    for (int j = 0; j < DOUT; ++j) {
        float lj = __shfl_sync(0xffffffffu, ls, j);
        if (lane < DOUT) {
            Usm[w][lane][j] = u[j];
            Vsm[w][lane][j] = u[j] * lj;
        }
    }
    __syncwarp();

    // triu(M) entries + linear head partials
    float res[10];
    #pragma unroll
    for (int o = 0; o < 10; ++o) res[o] = 0.f;

    for (int t = lane; t < NTRI; t += 32) {
        int i = 0, rem = t;
        while (rem >= DOUT - i) { rem -= DOUT - i; ++i; }
        int j = i + rem;
        float acc = 0.f;
        #pragma unroll
        for (int m = 0; m < DOUT; ++m)
            acc = fmaf(Vsm[w][i][m], Usm[w][j][m], acc);
        #pragma unroll
        for (int o = 0; o < 10; ++o)
            res[o] = fmaf(acc, lw[o * NTRI + t], res[o]);
    }
    // warp reduction
    #pragma unroll
    for (int o = 0; o < 10; ++o) {
        #pragma unroll
        for (int d = 16; d > 0; d >>= 1)
            res[o] += __shfl_xor_sync(0xffffffffu, res[o], d);
    }
    #pragma unroll
    for (int o = 0; o < 10; ++o)
        if (lane == o) out[(size_t)b * 10 + o] = res[o] + lb[o];
}

// ================= launch =================
extern "C" void kernel_launch(void* const* d_in, const int* in_sizes, int n_in,
                              void* d_out, int out_size) {
    const float* x  = (const float*)d_in[0];
    const float* W  = (const float*)d_in[1];
    const float* lw = (const float*)d_in[2];
    const float* lb = (const float*)d_in[3];
    float* out = (float*)d_out;

    cudaFuncSetAttribute(gram_kernel,
                         cudaFuncAttributeMaxDynamicSharedMemorySize,
                         (int)sizeof(SM1));
    gram_kernel<<<BATCH, 256, sizeof(SM1)>>>(x, W);
    eig_kernel<<<BATCH / 8, 256>>>(lw, lb, out);
}

// round 15
// speedup vs baseline: 2.5675x; 1.1402x over previous
#include <cuda_runtime.h>

#define BATCH 4096
#define CIN   64
#define NF    256
#define DOUT  20
#define NTRI  210
#define NSWEEP 6

// ---------------- scratch: Y matrices, layout Ysc[b*400 + j*20 + i] = Y[i][j]
__device__ float Ysc[BATCH * DOUT * DOUT];

// ================= K1: gram + kernel matrix + Y = W^T K W =================
struct SM1 {
    float xs[128][68];
    float G[CIN][65];
    float Wm[CIN][DOUT];
    float A64[CIN][DOUT];
    float rs[CIN][4];
    float mean[CIN];
    float sq[CIN];
};

__global__ __launch_bounds__(256, 3)
void gram_kernel(const float* __restrict__ x, const float* __restrict__ W)
{
    extern __shared__ char smraw[];
    SM1& s = *reinterpret_cast<SM1*>(smraw);
    const int b   = blockIdx.x;
    const int tid = threadIdx.x;
    const int c   = tid & 63;
    const int s2  = tid >> 6;
    const int ty  = tid >> 4, tx = tid & 15;

    for (int idx = tid; idx < CIN * DOUT; idx += 256)
        (&s.Wm[0][0])[idx] = W[idx];

    float acc[4][4];
    #pragma unroll
    for (int i = 0; i < 4; ++i)
        #pragma unroll
        for (int j = 0; j < 4; ++j) acc[i][j] = 0.f;
    float sumacc = 0.f;

    for (int ch = 0; ch < 2; ++ch) {
        const float* xp = x + ((size_t)b * CIN + c) * NF + ch * 128 + s2 * 32;
        #pragma unroll
        for (int i = 0; i < 8; ++i) {
            float4 v = *reinterpret_cast<const float4*>(xp + 4 * i);
            int n = s2 * 32 + 4 * i;
            s.xs[n + 0][c] = v.x; s.xs[n + 1][c] = v.y;
            s.xs[n + 2][c] = v.z; s.xs[n + 3][c] = v.w;
            sumacc += v.x + v.y + v.z + v.w;
        }
        __syncthreads();
        #pragma unroll 8
        for (int n = 0; n < 128; ++n) {
            float4 af = *reinterpret_cast<const float4*>(&s.xs[n][4 * ty]);
            float4 bf = *reinterpret_cast<const float4*>(&s.xs[n][4 * tx]);
            float av[4] = {af.x, af.y, af.z, af.w};
            float bv[4] = {bf.x, bf.y, bf.z, bf.w};
            #pragma unroll
            for (int i = 0; i < 4; ++i)
                #pragma unroll
                for (int j = 0; j < 4; ++j)
                    acc[i][j] = fmaf(av[i], bv[j], acc[i][j]);
        }
        __syncthreads();
    }

    s.rs[c][s2] = sumacc;
    #pragma unroll
    for (int i = 0; i < 4; ++i)
        #pragma unroll
        for (int j = 0; j < 4; ++j)
            s.G[4 * ty + i][4 * tx + j] = acc[i][j];
    __syncthreads();

    if (tid < CIN) {
        float m = (s.rs[tid][0] + s.rs[tid][1] + s.rs[tid][2] + s.rs[tid][3]) * (1.f / NF);
        s.mean[tid] = m;
        s.sq[tid]   = s.G[tid][tid] - (float)NF * m * m;
    }
    __syncthreads();

    #pragma unroll
    for (int i = 0; i < 4; ++i) {
        int cc = 4 * ty + i;
        float mc = s.mean[cc], sc = s.sq[cc];
        #pragma unroll
        for (int j = 0; j < 4; ++j) {
            int d = 4 * tx + j;
            float g  = s.G[cc][d] - (float)NF * mc * s.mean[d];
            float d2 = fmaxf(sc + s.sq[d] - 2.f * g, 0.f) * (1.f / NF);
            s.G[cc][d] = __expf(-50.f * d2);
        }
    }
    __syncthreads();

    {
        const int cr = tid >> 2;
        const int j0 = (tid & 3) * 5;
        float a0 = 0.f, a1 = 0.f, a2 = 0.f, a3 = 0.f, a4 = 0.f;
        #pragma unroll 4
        for (int d = 0; d < CIN; ++d) {
            float kk = s.G[cr][d];
            a0 = fmaf(kk, s.Wm[d][j0 + 0], a0);
            a1 = fmaf(kk, s.Wm[d][j0 + 1], a1);
            a2 = fmaf(kk, s.Wm[d][j0 + 2], a2);
            a3 = fmaf(kk, s.Wm[d][j0 + 3], a3);
            a4 = fmaf(kk, s.Wm[d][j0 + 4], a4);
        }
        s.A64[cr][j0 + 0] = a0; s.A64[cr][j0 + 1] = a1; s.A64[cr][j0 + 2] = a2;
        s.A64[cr][j0 + 3] = a3; s.A64[cr][j0 + 4] = a4;
    }
    __syncthreads();

    for (int t = tid; t < NTRI; t += 256) {
        int i = 0, rem = t;
        while (rem >= DOUT - i) { rem -= DOUT - i; ++i; }
        int j = i + rem;
        float a = 0.f;
        #pragma unroll 4
        for (int cc = 0; cc < CIN; ++cc)
            a = fmaf(s.Wm[cc][i], s.A64[cc][j], a);
        Ysc[(size_t)b * 400 + j * 20 + i] = a;
        Ysc[(size_t)b * 400 + i * 20 + j] = a;
    }
}

// ================= K2: warp-per-matrix Jacobi, fused col rotation =================
struct Sched { int p[19][10]; int q[19][10]; };
__host__ __device__ constexpr Sched mksched() {
    Sched s{};
    for (int r = 0; r < 19; ++r)
        for (int k = 0; k < 10; ++k) {
            int a = (k == 0) ? 0 : ((k - 1 + r) % 19) + 1;
            int b = ((18 - k + r) % 19) + 1;
            s.p[r][k] = a < b ? a : b;
            s.q[r][k] = a > b ? a : b;
        }
    return s;
}

__global__ __launch_bounds__(256, 4)
void eig_kernel(const float* __restrict__ lw, const float* __restrict__ lb,
                float* __restrict__ out)
{
    constexpr Sched S = mksched();
    const int w    = threadIdx.x >> 5;
    const int lane = threadIdx.x & 31;
    const int b    = blockIdx.x * 8 + w;

    __shared__ float Usm[8][DOUT][21];
    __shared__ float Vsm[8][DOUT][21];

    float a[DOUT], u[DOUT];
    #pragma unroll
    for (int j = 0; j < DOUT; ++j) {
        a[j] = (lane < DOUT) ? Ysc[(size_t)b * 400 + j * 20 + lane] : 0.f;
        u[j] = (lane == j) ? 1.f : 0.f;
    }

    #pragma unroll 1
    for (int sweep = 0; sweep < NSWEEP; ++sweep) {
        #pragma unroll
        for (int r = 0; r < 19; ++r) {
            float cr = 1.f, tr = 0.f;
            int prt = lane;
            // per pair: angle from pristine columns, then immediate col rotation
            #pragma unroll
            for (int k = 0; k < 10; ++k) {
                const int P = S.p[r][k], Q = S.q[r][k];
                float app = __shfl_sync(0xffffffffu, a[P], P);
                float aqq = __shfl_sync(0xffffffffu, a[Q], Q);
                float apq = __shfl_sync(0xffffffffu, a[Q], P);
                float c1, s1;
                if (fabsf(apq) > 1e-30f) {
                    // t = 2*apq*sign(d) / (|d| + sqrt(d^2 + 4*apq^2)), d = aqq-app
                    // (same tangent as sign(th)/(|th|+sqrt(th^2+1)); 3 MUFU not 4)
                    float d   = aqq - app;
                    float h   = fmaf(d, d, 4.f * apq * apq);
                    float den = fabsf(d) + sqrtf(h);       // >= 2|apq| > 0
                    float t1  = 2.f * apq * copysignf(__frcp_rn(den), d);
                    c1 = rsqrtf(fmaf(t1, t1, 1.f));
                    s1 = t1 * c1;
                } else { c1 = 1.f; s1 = 0.f; }
                if (lane == P) { cr = c1; tr = -s1; prt = Q; }
                if (lane == Q) { cr = c1; tr =  s1; prt = P; }
                // col rotation: A <- A J, U <- U J (lane-local, disjoint columns)
                float ap = a[P], aq = a[Q];
                a[P] = fmaf(c1, ap, -s1 * aq);
                a[Q] = fmaf(s1, ap,  c1 * aq);
                float up = u[P], uq = u[Q];
                u[P] = fmaf(c1, up, -s1 * uq);
                u[Q] = fmaf(s1, up,  c1 * uq);
            }
            // row phase: A <- J^T A (on the col-updated matrix; J^T(AJ) = (J^T A)J)
            #pragma unroll
            for (int j = 0; j < DOUT; ++j) {
                float o = __shfl_sync(0xffffffffu, a[j], prt);
                a[j] = fmaf(cr, a[j], tr * o);
            }
        }
    }

    // eigenvalue of this lane's row = diagonal element
    float lam = 1.f;
    #pragma unroll
    for (int j = 0; j < DOUT; ++j)
        if (lane == j) lam = a[j];
    float ls = logf(fmaxf(lam, 1e-4f));

    // stage U and U*diag(logS) rows to smem
    #pragma unroll
    for (int j = 0; j < DOUT; ++j) {
        float lj = __shfl_sync(0xffffffffu, ls, j);
        if (lane < DOUT) {
            Usm[w][lane][j] = u[j];
            Vsm[w][lane][j] = u[j] * lj;
        }
    }
    __syncwarp();

    // triu(M) entries + linear head partials
    float res[10];
    #pragma unroll
    for (int o = 0; o < 10; ++o) res[o] = 0.f;

    for (int t = lane; t < NTRI; t += 32) {
        int i = 0, rem = t;
        while (rem >= DOUT - i) { rem -= DOUT - i; ++i; }
        int j = i + rem;
        float acc = 0.f;
        #pragma unroll
        for (int m = 0; m < DOUT; ++m)
            acc = fmaf(Vsm[w][i][m], Usm[w][j][m], acc);
        #pragma unroll
        for (int o = 0; o < 10; ++o)
            res[o] = fmaf(acc, lw[o * NTRI + t], res[o]);
    }
    // warp reduction
    #pragma unroll
    for (int o = 0; o < 10; ++o) {
        #pragma unroll
        for (int d = 16; d > 0; d >>= 1)
            res[o] += __shfl_xor_sync(0xffffffffu, res[o], d);
    }
    #pragma unroll
    for (int o = 0; o < 10; ++o)
        if (lane == o) out[(size_t)b * 10 + o] = res[o] + lb[o];
}

// ================= launch =================
extern "C" void kernel_launch(void* const* d_in, const int* in_sizes, int n_in,
                              void* d_out, int out_size) {
    const float* x  = (const float*)d_in[0];
    const float* W  = (const float*)d_in[1];
    const float* lw = (const float*)d_in[2];
    const float* lb = (const float*)d_in[3];
    float* out = (float*)d_out;

    cudaFuncSetAttribute(gram_kernel,
                         cudaFuncAttributeMaxDynamicSharedMemorySize,
                         (int)sizeof(SM1));
    gram_kernel<<<BATCH, 256, sizeof(SM1)>>>(x, W);
    eig_kernel<<<BATCH / 8, 256>>>(lw, lb, out);
}

// round 16
// speedup vs baseline: 2.9351x; 1.1432x over previous
#include <cuda_runtime.h>

#define BATCH 4096
#define CIN   64
#define NF    256
#define DOUT  20
#define NTRI  210
#define NSWEEP 5

// ---------------- scratch: Y matrices, layout Ysc[b*400 + j*20 + i] = Y[i][j]
__device__ float Ysc[BATCH * DOUT * DOUT];

// ================= K1: gram + kernel matrix + Y = W^T K W =================
struct SM1 {
    float xs[128][68];
    float G[CIN][65];
    float Wm[CIN][DOUT];
    float A64[CIN][DOUT];
    float rs[CIN][4];
    float mean[CIN];
    float sq[CIN];
};

__global__ __launch_bounds__(256, 3)
void gram_kernel(const float* __restrict__ x, const float* __restrict__ W)
{
    extern __shared__ char smraw[];
    SM1& s = *reinterpret_cast<SM1*>(smraw);
    const int b   = blockIdx.x;
    const int tid = threadIdx.x;
    const int c   = tid & 63;
    const int s2  = tid >> 6;
    const int ty  = tid >> 4, tx = tid & 15;

    for (int idx = tid; idx < CIN * DOUT; idx += 256)
        (&s.Wm[0][0])[idx] = W[idx];

    float acc[4][4];
    #pragma unroll
    for (int i = 0; i < 4; ++i)
        #pragma unroll
        for (int j = 0; j < 4; ++j) acc[i][j] = 0.f;
    float sumacc = 0.f;

    for (int ch = 0; ch < 2; ++ch) {
        const float* xp = x + ((size_t)b * CIN + c) * NF + ch * 128 + s2 * 32;
        #pragma unroll
        for (int i = 0; i < 8; ++i) {
            float4 v = *reinterpret_cast<const float4*>(xp + 4 * i);
            int n = s2 * 32 + 4 * i;
            s.xs[n + 0][c] = v.x; s.xs[n + 1][c] = v.y;
            s.xs[n + 2][c] = v.z; s.xs[n + 3][c] = v.w;
            sumacc += v.x + v.y + v.z + v.w;
        }
        __syncthreads();
        #pragma unroll 8
        for (int n = 0; n < 128; ++n) {
            float4 af = *reinterpret_cast<const float4*>(&s.xs[n][4 * ty]);
            float4 bf = *reinterpret_cast<const float4*>(&s.xs[n][4 * tx]);
            float av[4] = {af.x, af.y, af.z, af.w};
            float bv[4] = {bf.x, bf.y, bf.z, bf.w};
            #pragma unroll
            for (int i = 0; i < 4; ++i)
                #pragma unroll
                for (int j = 0; j < 4; ++j)
                    acc[i][j] = fmaf(av[i], bv[j], acc[i][j]);
        }
        __syncthreads();
    }

    s.rs[c][s2] = sumacc;
    #pragma unroll
    for (int i = 0; i < 4; ++i)
        #pragma unroll
        for (int j = 0; j < 4; ++j)
            s.G[4 * ty + i][4 * tx + j] = acc[i][j];
    __syncthreads();

    if (tid < CIN) {
        float m = (s.rs[tid][0] + s.rs[tid][1] + s.rs[tid][2] + s.rs[tid][3]) * (1.f / NF);
        s.mean[tid] = m;
        s.sq[tid]   = s.G[tid][tid] - (float)NF * m * m;
    }
    __syncthreads();

    #pragma unroll
    for (int i = 0; i < 4; ++i) {
        int cc = 4 * ty + i;
        float mc = s.mean[cc], sc = s.sq[cc];
        #pragma unroll
        for (int j = 0; j < 4; ++j) {
            int d = 4 * tx + j;
            float g  = s.G[cc][d] - (float)NF * mc * s.mean[d];
            float d2 = fmaxf(sc + s.sq[d] - 2.f * g, 0.f) * (1.f / NF);
            s.G[cc][d] = __expf(-50.f * d2);
        }
    }
    __syncthreads();

    {
        const int cr = tid >> 2;
        const int j0 = (tid & 3) * 5;
        float a0 = 0.f, a1 = 0.f, a2 = 0.f, a3 = 0.f, a4 = 0.f;
        #pragma unroll 4
        for (int d = 0; d < CIN; ++d) {
            float kk = s.G[cr][d];
            a0 = fmaf(kk, s.Wm[d][j0 + 0], a0);
            a1 = fmaf(kk, s.Wm[d][j0 + 1], a1);
            a2 = fmaf(kk, s.Wm[d][j0 + 2], a2);
            a3 = fmaf(kk, s.Wm[d][j0 + 3], a3);
            a4 = fmaf(kk, s.Wm[d][j0 + 4], a4);
        }
        s.A64[cr][j0 + 0] = a0; s.A64[cr][j0 + 1] = a1; s.A64[cr][j0 + 2] = a2;
        s.A64[cr][j0 + 3] = a3; s.A64[cr][j0 + 4] = a4;
    }
    __syncthreads();

    for (int t = tid; t < NTRI; t += 256) {
        int i = 0, rem = t;
        while (rem >= DOUT - i) { rem -= DOUT - i; ++i; }
        int j = i + rem;
        float a = 0.f;
        #pragma unroll 4
        for (int cc = 0; cc < CIN; ++cc)
            a = fmaf(s.Wm[cc][i], s.A64[cc][j], a);
        Ysc[(size_t)b * 400 + j * 20 + i] = a;
        Ysc[(size_t)b * 400 + i * 20 + j] = a;
    }
}

// ================= K2: warp-per-matrix Jacobi, fused col rotation =================
struct Sched { int p[19][10]; int q[19][10]; };
__host__ __device__ constexpr Sched mksched() {
    Sched s{};
    for (int r = 0; r < 19; ++r)
        for (int k = 0; k < 10; ++k) {
            int a = (k == 0) ? 0 : ((k - 1 + r) % 19) + 1;
            int b = ((18 - k + r) % 19) + 1;
            s.p[r][k] = a < b ? a : b;
            s.q[r][k] = a > b ? a : b;
        }
    return s;
}

__global__ __launch_bounds__(256, 4)
void eig_kernel(const float* __restrict__ lw, const float* __restrict__ lb,
                float* __restrict__ out)
{
    constexpr Sched S = mksched();
    const int w    = threadIdx.x >> 5;
    const int lane = threadIdx.x & 31;
    const int b    = blockIdx.x * 8 + w;

    __shared__ float Usm[8][DOUT][21];
    __shared__ float Vsm[8][DOUT][21];

    float a[DOUT], u[DOUT];
    #pragma unroll
    for (int j = 0; j < DOUT; ++j) {
        a[j] = (lane < DOUT) ? Ysc[(size_t)b * 400 + j * 20 + lane] : 0.f;
        u[j] = (lane == j) ? 1.f : 0.f;
    }

    #pragma unroll 1
    for (int sweep = 0; sweep < NSWEEP; ++sweep) {
        #pragma unroll
        for (int r = 0; r < 19; ++r) {
            float cr = 1.f, tr = 0.f;
            int prt = lane;
            // per pair: branchless angle from pristine columns, then col rotation
            #pragma unroll
            for (int k = 0; k < 10; ++k) {
                const int P = S.p[r][k], Q = S.q[r][k];
                float app = __shfl_sync(0xffffffffu, a[P], P);
                float aqq = __shfl_sync(0xffffffffu, a[Q], Q);
                float apq = __shfl_sync(0xffffffffu, a[Q], P);
                // t = 2*apq*sign(d) / (|d| + sqrt(d^2 + 4*apq^2)), d = aqq-app
                // +1e-35 only matters at d=apq=0 (kills 0*inf=NaN; gives t=0).
                float d   = aqq - app;
                float h   = fmaf(d, d, 4.f * apq * apq);
                float den = fabsf(d) + sqrtf(h) + 1e-35f;
                float t1  = 2.f * apq * copysignf(__frcp_rn(den), d);
                float c1  = rsqrtf(fmaf(t1, t1, 1.f));
                float s1  = t1 * c1;
                if (lane == P) { cr = c1; tr = -s1; prt = Q; }
                if (lane == Q) { cr = c1; tr =  s1; prt = P; }
                // col rotation: A <- A J, U <- U J (lane-local, disjoint columns)
                float ap = a[P], aq = a[Q];
                a[P] = fmaf(c1, ap, -s1 * aq);
                a[Q] = fmaf(s1, ap,  c1 * aq);
                float up = u[P], uq = u[Q];
                u[P] = fmaf(c1, up, -s1 * uq);
                u[Q] = fmaf(s1, up,  c1 * uq);
            }
            // row phase: A <- J^T A (on the col-updated matrix; J^T(AJ) = (J^T A)J)
            #pragma unroll
            for (int j = 0; j < DOUT; ++j) {
                float o = __shfl_sync(0xffffffffu, a[j], prt);
                a[j] = fmaf(cr, a[j], tr * o);
            }
        }
    }

    // eigenvalue of this lane's row = diagonal element
    float lam = 1.f;
    #pragma unroll
    for (int j = 0; j < DOUT; ++j)
        if (lane == j) lam = a[j];
    float ls = logf(fmaxf(lam, 1e-4f));

    // stage U and U*diag(logS) rows to smem
    #pragma unroll
    for (int j = 0; j < DOUT; ++j) {
        float lj = __shfl_sync(0xffffffffu, ls, j);
        if (lane < DOUT) {
            Usm[w][lane][j] = u[j];
            Vsm[w][lane][j] = u[j] * lj;
        }
    }
    __syncwarp();

    // triu(M) entries + linear head partials
    float res[10];
    #pragma unroll
    for (int o = 0; o < 10; ++o) res[o] = 0.f;

    for (int t = lane; t < NTRI; t += 32) {
        int i = 0, rem = t;
        while (rem >= DOUT - i) { rem -= DOUT - i; ++i; }
        int j = i + rem;
        float acc = 0.f;
        #pragma unroll
        for (int m = 0; m < DOUT; ++m)
            acc = fmaf(Vsm[w][i][m], Usm[w][j][m], acc);
        #pragma unroll
        for (int o = 0; o < 10; ++o)
            res[o] = fmaf(acc, lw[o * NTRI + t], res[o]);
    }
    // warp reduction
    #pragma unroll
    for (int o = 0; o < 10; ++o) {
        #pragma unroll
        for (int d = 16; d > 0; d >>= 1)
            res[o] += __shfl_xor_sync(0xffffffffu, res[o], d);
    }
    #pragma unroll
    for (int o = 0; o < 10; ++o)
        if (lane == o) out[(size_t)b * 10 + o] = res[o] + lb[o];
}

// ================= launch =================
extern "C" void kernel_launch(void* const* d_in, const int* in_sizes, int n_in,
                              void* d_out, int out_size) {
    const float* x  = (const float*)d_in[0];
    const float* W  = (const float*)d_in[1];
    const float* lw = (const float*)d_in[2];
    const float* lb = (const float*)d_in[3];
    float* out = (float*)d_out;

    cudaFuncSetAttribute(gram_kernel,
                         cudaFuncAttributeMaxDynamicSharedMemorySize,
                         (int)sizeof(SM1));
    gram_kernel<<<BATCH, 256, sizeof(SM1)>>>(x, W);
    eig_kernel<<<BATCH / 8, 256>>>(lw, lb, out);
}